// round 3
// baseline (speedup 1.0000x reference)
#include <cuda_runtime.h>
#include <math.h>

#define N_TOK 32768
#define DIMX  512
#define HID   2048
#define NEXP  16

// ---------------- scratch (static device globals; no runtime allocation) ----
__device__ int   g_leaf[N_TOK];
__device__ int   g_cnt[NEXP];
__device__ int   g_off[NEXP + 1];
__device__ int   g_cur[NEXP];
__device__ int   g_perm[N_TOK];
__device__ float g_h[(size_t)N_TOK * HID];   // 256 MB intermediate activations

// ---------------- tiny helpers ---------------------------------------------
__global__ void k_zero() {
    if (threadIdx.x < NEXP) g_cnt[threadIdx.x] = 0;
}

// One warp per token. x row cached in registers, 4 router dot products.
__global__ void k_route(const float* __restrict__ x,
                        const float* __restrict__ Wr,
                        const float* __restrict__ br) {
    int warp = (blockIdx.x * blockDim.x + threadIdx.x) >> 5;
    int lane = threadIdx.x & 31;
    const float4* xp = (const float4*)(x + (size_t)warp * DIMX);
    float4 xr[4];
#pragma unroll
    for (int j = 0; j < 4; j++) xr[j] = xp[lane + 32 * j];
    int leaf = 0;
#pragma unroll
    for (int d = 0; d < 4; d++) {
        int r = (1 << d) - 1 + leaf;
        const float4* wp = (const float4*)(Wr + (size_t)r * DIMX);
        float s = 0.f;
#pragma unroll
        for (int j = 0; j < 4; j++) {
            float4 w = wp[lane + 32 * j];
            s += xr[j].x * w.x; s += xr[j].y * w.y;
            s += xr[j].z * w.z; s += xr[j].w * w.w;
        }
#pragma unroll
        for (int o = 16; o; o >>= 1) s += __shfl_xor_sync(0xffffffffu, s, o);
        leaf = leaf * 2 + (((s + br[r]) > 0.f) ? 1 : 0);
    }
    if (lane == 0) {
        g_leaf[warp] = leaf;
        atomicAdd(&g_cnt[leaf], 1);
    }
}

__global__ void k_prefix() {
    int acc = 0;
    for (int e = 0; e < NEXP; e++) {
        g_off[e] = acc;
        g_cur[e] = acc;
        acc += g_cnt[e];
    }
    g_off[NEXP] = acc;
}

__global__ void k_scatter() {
    int n = blockIdx.x * blockDim.x + threadIdx.x;
    int pos = atomicAdd(&g_cur[g_leaf[n]], 1);
    g_perm[pos] = n;
}

// ---------------- grouped GEMM 1: h = gelu(x[perm] @ W1[e] + b1[e]) ---------
// Tile: BM=128, BN=64, BK=16, 256 threads, 8x4 accumulators per thread.
__global__ __launch_bounds__(256)
void k_ffn1(const float* __restrict__ x,
            const float* __restrict__ W1,
            const float* __restrict__ b1) {
    const int e  = blockIdx.z;
    const int M  = g_cnt[e];
    const int m0 = blockIdx.y * 128;
    if (m0 >= M) return;
    const int n0  = blockIdx.x * 64;
    const int tid = threadIdx.x;
    const int tx  = tid & 15;          // 0..15  (4 output cols each)
    const int ty  = tid >> 4;          // 0..15  (8 output rows each)

    __shared__ float As[16 * 128];     // [k][row]  (transposed)
    __shared__ float Bs[16 * 68];      // [k][n]    (padded stride 68)

    const int   ooff = g_off[e];
    const float* Bg  = W1 + (size_t)e * DIMX * HID + n0;
    const float* b1p = b1 + e * HID + n0;

    // A producer mapping: thread covers row = tid/2, k-offsets (tid&1)*8 .. +7
    const int  arow   = tid >> 1;
    const int  akq    = (tid & 1) * 8;
    const bool avalid = (m0 + arow) < M;
    const float* aptr = avalid ? (x + (size_t)g_perm[ooff + m0 + arow] * DIMX) : x;

    // B producer mapping: row = tid>>4 (0..15), col quad = tid&15
    const int brow = tid >> 4;
    const int bq   = tid & 15;

    float acc[8][4];
#pragma unroll
    for (int r = 0; r < 8; r++)
#pragma unroll
        for (int c = 0; c < 4; c++) acc[r][c] = 0.f;

    for (int k0 = 0; k0 < DIMX; k0 += 16) {
        float4 a0 = make_float4(0.f, 0.f, 0.f, 0.f), a1 = a0;
        if (avalid) {
            a0 = *(const float4*)(aptr + k0 + akq);
            a1 = *(const float4*)(aptr + k0 + akq + 4);
        }
        float4 bv = *(const float4*)(Bg + (size_t)(k0 + brow) * HID + bq * 4);

        __syncthreads();
        As[(akq + 0) * 128 + arow] = a0.x;
        As[(akq + 1) * 128 + arow] = a0.y;
        As[(akq + 2) * 128 + arow] = a0.z;
        As[(akq + 3) * 128 + arow] = a0.w;
        As[(akq + 4) * 128 + arow] = a1.x;
        As[(akq + 5) * 128 + arow] = a1.y;
        As[(akq + 6) * 128 + arow] = a1.z;
        As[(akq + 7) * 128 + arow] = a1.w;
        *(float4*)&Bs[brow * 68 + bq * 4] = bv;
        __syncthreads();

#pragma unroll
        for (int kk = 0; kk < 16; kk++) {
            float4 af0 = *(const float4*)&As[kk * 128 + ty * 8];
            float4 af1 = *(const float4*)&As[kk * 128 + ty * 8 + 4];
            float4 bf  = *(const float4*)&Bs[kk * 68 + tx * 4];
            float ar[8] = {af0.x, af0.y, af0.z, af0.w, af1.x, af1.y, af1.z, af1.w};
            float bb[4] = {bf.x, bf.y, bf.z, bf.w};
#pragma unroll
            for (int r = 0; r < 8; r++)
#pragma unroll
                for (int c = 0; c < 4; c++) acc[r][c] += ar[r] * bb[c];
        }
    }

#pragma unroll
    for (int r = 0; r < 8; r++) {
        int row = ty * 8 + r;
        if (m0 + row < M) {
            float4 o;
            float v0 = acc[r][0] + b1p[tx * 4 + 0];
            float v1 = acc[r][1] + b1p[tx * 4 + 1];
            float v2 = acc[r][2] + b1p[tx * 4 + 2];
            float v3 = acc[r][3] + b1p[tx * 4 + 3];
            o.x = 0.5f * v0 * (1.f + erff(v0 * 0.7071067811865476f));
            o.y = 0.5f * v1 * (1.f + erff(v1 * 0.7071067811865476f));
            o.z = 0.5f * v2 * (1.f + erff(v2 * 0.7071067811865476f));
            o.w = 0.5f * v3 * (1.f + erff(v3 * 0.7071067811865476f));
            *(float4*)(g_h + (size_t)(ooff + m0 + row) * HID + n0 + tx * 4) = o;
        }
    }
}

// ---------------- grouped GEMM 2: out[perm] = h @ W2[e] + b2[e] -------------
__global__ __launch_bounds__(256)
void k_ffn2(const float* __restrict__ W2,
            const float* __restrict__ b2,
            float* __restrict__ out) {
    const int e  = blockIdx.z;
    const int M  = g_cnt[e];
    const int m0 = blockIdx.y * 128;
    if (m0 >= M) return;
    const int n0  = blockIdx.x * 64;
    const int tid = threadIdx.x;
    const int tx  = tid & 15;
    const int ty  = tid >> 4;

    __shared__ float As[16 * 128];
    __shared__ float Bs[16 * 68];

    const int   ooff = g_off[e];
    const float* Bg  = W2 + (size_t)e * HID * DIMX + n0;
    const float* b2p = b2 + e * DIMX + n0;

    const int  arow   = tid >> 1;
    const int  akq    = (tid & 1) * 8;
    const bool avalid = (m0 + arow) < M;
    const float* aptr = avalid ? (g_h + (size_t)(ooff + m0 + arow) * HID) : g_h;

    const int brow = tid >> 4;
    const int bq   = tid & 15;

    float acc[8][4];
#pragma unroll
    for (int r = 0; r < 8; r++)
#pragma unroll
        for (int c = 0; c < 4; c++) acc[r][c] = 0.f;

    for (int k0 = 0; k0 < HID; k0 += 16) {
        float4 a0 = make_float4(0.f, 0.f, 0.f, 0.f), a1 = a0;
        if (avalid) {
            a0 = *(const float4*)(aptr + k0 + akq);
            a1 = *(const float4*)(aptr + k0 + akq + 4);
        }
        float4 bv = *(const float4*)(Bg + (size_t)(k0 + brow) * DIMX + bq * 4);

        __syncthreads();
        As[(akq + 0) * 128 + arow] = a0.x;
        As[(akq + 1) * 128 + arow] = a0.y;
        As[(akq + 2) * 128 + arow] = a0.z;
        As[(akq + 3) * 128 + arow] = a0.w;
        As[(akq + 4) * 128 + arow] = a1.x;
        As[(akq + 5) * 128 + arow] = a1.y;
        As[(akq + 6) * 128 + arow] = a1.z;
        As[(akq + 7) * 128 + arow] = a1.w;
        *(float4*)&Bs[brow * 68 + bq * 4] = bv;
        __syncthreads();

#pragma unroll
        for (int kk = 0; kk < 16; kk++) {
            float4 af0 = *(const float4*)&As[kk * 128 + ty * 8];
            float4 af1 = *(const float4*)&As[kk * 128 + ty * 8 + 4];
            float4 bf  = *(const float4*)&Bs[kk * 68 + tx * 4];
            float ar[8] = {af0.x, af0.y, af0.z, af0.w, af1.x, af1.y, af1.z, af1.w};
            float bb[4] = {bf.x, bf.y, bf.z, bf.w};
#pragma unroll
            for (int r = 0; r < 8; r++)
#pragma unroll
                for (int c = 0; c < 4; c++) acc[r][c] += ar[r] * bb[c];
        }
    }

#pragma unroll
    for (int r = 0; r < 8; r++) {
        int row = ty * 8 + r;
        if (m0 + row < M) {
            int orow = g_perm[ooff + m0 + row];
            float4 o;
            o.x = acc[r][0] + b2p[tx * 4 + 0];
            o.y = acc[r][1] + b2p[tx * 4 + 1];
            o.z = acc[r][2] + b2p[tx * 4 + 2];
            o.w = acc[r][3] + b2p[tx * 4 + 3];
            *(float4*)(out + (size_t)orow * DIMX + n0 + tx * 4) = o;
        }
    }
}

// ---------------- launch -----------------------------------------------------
extern "C" void kernel_launch(void* const* d_in, const int* in_sizes, int n_in,
                              void* d_out, int out_size) {
    const float* x  = (const float*)d_in[0];
    const float* Wr = (const float*)d_in[1];
    const float* br = (const float*)d_in[2];
    const float* W1 = (const float*)d_in[3];
    const float* b1 = (const float*)d_in[4];
    const float* W2 = (const float*)d_in[5];
    const float* b2 = (const float*)d_in[6];
    float* out = (float*)d_out;

    k_zero<<<1, 32>>>();
    k_route<<<N_TOK / 8, 256>>>(x, Wr, br);      // 8 warps per block
    k_prefix<<<1, 1>>>();
    k_scatter<<<N_TOK / 256, 256>>>();
    // worst case: all tokens in one expert -> 256 M-tiles of 128
    k_ffn1<<<dim3(HID / 64, 256, NEXP), 256>>>(x, W1, b1);
    k_ffn2<<<dim3(DIMX / 64, 256, NEXP), 256>>>(W2, b2, out);
}

// round 6
// speedup vs baseline: 1.5905x; 1.5905x over previous
#include <cuda_runtime.h>
#include <cuda_bf16.h>
#include <stdint.h>
#include <math.h>

#define N_TOK 32768
#define DIMX  512
#define HID   2048
#define NEXP  16

// ---------------- scratch (static device globals; no runtime allocation) ----
__device__ int   g_leaf[N_TOK];
__device__ int   g_cnt[NEXP];
__device__ int   g_off[NEXP + 1];
__device__ int   g_cur[NEXP];
__device__ int   g_perm[N_TOK];
__device__ float g_h[(size_t)N_TOK * HID];   // 256 MB intermediate activations

// ---------------- tiny helpers ---------------------------------------------
__global__ void k_zero() {
    if (threadIdx.x < NEXP) g_cnt[threadIdx.x] = 0;
}

// One warp per token. x row cached in registers, 4 router dot products.
__global__ void k_route(const float* __restrict__ x,
                        const float* __restrict__ Wr,
                        const float* __restrict__ br) {
    int warp = (blockIdx.x * blockDim.x + threadIdx.x) >> 5;
    int lane = threadIdx.x & 31;
    const float4* xp = (const float4*)(x + (size_t)warp * DIMX);
    float4 xr[4];
#pragma unroll
    for (int j = 0; j < 4; j++) xr[j] = xp[lane + 32 * j];
    int leaf = 0;
#pragma unroll
    for (int d = 0; d < 4; d++) {
        int r = (1 << d) - 1 + leaf;
        const float4* wp = (const float4*)(Wr + (size_t)r * DIMX);
        float s = 0.f;
#pragma unroll
        for (int j = 0; j < 4; j++) {
            float4 w = wp[lane + 32 * j];
            s += xr[j].x * w.x; s += xr[j].y * w.y;
            s += xr[j].z * w.z; s += xr[j].w * w.w;
        }
#pragma unroll
        for (int o = 16; o; o >>= 1) s += __shfl_xor_sync(0xffffffffu, s, o);
        leaf = leaf * 2 + (((s + br[r]) > 0.f) ? 1 : 0);
    }
    if (lane == 0) {
        g_leaf[warp] = leaf;
        atomicAdd(&g_cnt[leaf], 1);
    }
}

__global__ void k_prefix() {
    int acc = 0;
    for (int e = 0; e < NEXP; e++) {
        g_off[e] = acc;
        g_cur[e] = acc;
        acc += g_cnt[e];
    }
    g_off[NEXP] = acc;
}

__global__ void k_scatter() {
    int n = blockIdx.x * blockDim.x + threadIdx.x;
    int pos = atomicAdd(&g_cur[g_leaf[n]], 1);
    g_perm[pos] = n;
}

// ---------------- bf16 split helpers ----------------------------------------
__device__ __forceinline__ void split2(float x, float y, uint32_t& wh, uint32_t& wl) {
    __nv_bfloat16 hx = __float2bfloat16_rn(x);
    __nv_bfloat16 hy = __float2bfloat16_rn(y);
    __nv_bfloat16 lx = __float2bfloat16_rn(x - __bfloat162float(hx));
    __nv_bfloat16 ly = __float2bfloat16_rn(y - __bfloat162float(hy));
    __nv_bfloat162 H; H.x = hx; H.y = hy;
    __nv_bfloat162 L; L.x = lx; L.y = ly;
    wh = *reinterpret_cast<uint32_t*>(&H);
    wl = *reinterpret_cast<uint32_t*>(&L);
}

__device__ __forceinline__ void mma_bf16(float* c, const uint32_t* a, const uint32_t* b) {
    asm volatile(
        "mma.sync.aligned.m16n8k16.row.col.f32.bf16.bf16.f32 "
        "{%0,%1,%2,%3}, {%4,%5,%6,%7}, {%8,%9}, {%0,%1,%2,%3};"
        : "+f"(c[0]), "+f"(c[1]), "+f"(c[2]), "+f"(c[3])
        : "r"(a[0]), "r"(a[1]), "r"(a[2]), "r"(a[3]), "r"(b[0]), "r"(b[1]));
}

// ---------------- grouped GEMM (tensor-core, bf16x3 split) -------------------
// Tile: BM=128, BN=64, BK=16. 8 warps in 4(M)x2(N); each warp computes 32x32.
// A smem: bf16x2 words [row 128][word 12] (words 0..7 used, pad for banks).
// B smem: transposed, bf16 [n 64][k 18] (k-pairs contiguous for B fragments).
template<int KDIM, int NDIM, bool FFN1>
__global__ __launch_bounds__(256)
void k_gemm(const float* __restrict__ Asrc, const float* __restrict__ W,
            const float* __restrict__ bias, float* __restrict__ Dst) {
    const int e  = blockIdx.z;
    const int M  = g_cnt[e];
    const int m0 = blockIdx.y * 128;
    if (m0 >= M) return;
    const int n0   = blockIdx.x * 64;
    const int tid  = threadIdx.x;
    const int lane = tid & 31;
    const int wm   = (tid >> 5) >> 1;   // 0..3
    const int wn   = (tid >> 5) & 1;    // 0..1
    const int ooff = g_off[e];

    __shared__ uint32_t       sAh[128][12];
    __shared__ uint32_t       sAl[128][12];
    __shared__ __nv_bfloat16  sBh[64 * 18];
    __shared__ __nv_bfloat16  sBl[64 * 18];

    // A producer: 2 rows per thread (ar0, ar0+64), 4 cols starting at ac.
    const int ar0 = tid >> 2, ar1 = ar0 + 64;
    const int ac  = (tid & 3) * 4;
    const int aw  = (tid & 3) * 2;      // word index (2 words per float4)
    const bool av0 = (m0 + ar0) < M, av1 = (m0 + ar1) < M;
    const float *ap0, *ap1;
    if (FFN1) {
        ap0 = Asrc + (size_t)(av0 ? g_perm[ooff + m0 + ar0] : 0) * KDIM;
        ap1 = Asrc + (size_t)(av1 ? g_perm[ooff + m0 + ar1] : 0) * KDIM;
    } else {
        ap0 = Asrc + (size_t)(av0 ? (ooff + m0 + ar0) : 0) * KDIM;
        ap1 = Asrc + (size_t)(av1 ? (ooff + m0 + ar1) : 0) * KDIM;
    }
    // B producer: one k-row (bkr), 4 n-cols (bnc..bnc+3).
    const int bkr = tid >> 4;           // 0..15
    const int bnc = (tid & 15) * 4;     // 0..60
    const float* Bg = W + (size_t)e * KDIM * NDIM + n0 + bnc;

    float4 ra0 = *(const float4*)(ap0 + ac);
    float4 ra1 = *(const float4*)(ap1 + ac);
    float4 rb  = *(const float4*)(Bg + (size_t)bkr * NDIM);

    float acc[2][4][4];
#pragma unroll
    for (int mt = 0; mt < 2; mt++)
#pragma unroll
        for (int nt = 0; nt < 4; nt++)
#pragma unroll
            for (int i = 0; i < 4; i++) acc[mt][nt][i] = 0.f;

    for (int k0 = 0; k0 < KDIM; k0 += 16) {
        // ---- stage registers -> smem (hi/lo split) ----
        {
            uint32_t h0, l0, h1, l1;
            split2(ra0.x, ra0.y, h0, l0);
            split2(ra0.z, ra0.w, h1, l1);
            sAh[ar0][aw] = h0; sAh[ar0][aw + 1] = h1;
            sAl[ar0][aw] = l0; sAl[ar0][aw + 1] = l1;
            split2(ra1.x, ra1.y, h0, l0);
            split2(ra1.z, ra1.w, h1, l1);
            sAh[ar1][aw] = h0; sAh[ar1][aw + 1] = h1;
            sAl[ar1][aw] = l0; sAl[ar1][aw + 1] = l1;

            float bv[4] = {rb.x, rb.y, rb.z, rb.w};
#pragma unroll
            for (int i = 0; i < 4; i++) {
                __nv_bfloat16 bh = __float2bfloat16_rn(bv[i]);
                __nv_bfloat16 bl = __float2bfloat16_rn(bv[i] - __bfloat162float(bh));
                sBh[(bnc + i) * 18 + bkr] = bh;
                sBl[(bnc + i) * 18 + bkr] = bl;
            }
        }
        __syncthreads();

        // ---- prefetch next chunk ----
        if (k0 + 16 < KDIM) {
            ra0 = *(const float4*)(ap0 + k0 + 16 + ac);
            ra1 = *(const float4*)(ap1 + k0 + 16 + ac);
            rb  = *(const float4*)(Bg + (size_t)(k0 + 16 + bkr) * NDIM);
        }

        // ---- consume: load fragments, 24 MMAs ----
        {
            const int t = lane & 3, g = lane >> 2;
            uint32_t Ah[2][4], Al[2][4], Bh[4][2], Bl[4][2];
#pragma unroll
            for (int mt = 0; mt < 2; mt++) {
                int row = wm * 32 + mt * 16 + g;
                Ah[mt][0] = sAh[row    ][t];
                Ah[mt][1] = sAh[row + 8][t];
                Ah[mt][2] = sAh[row    ][t + 4];
                Ah[mt][3] = sAh[row + 8][t + 4];
                Al[mt][0] = sAl[row    ][t];
                Al[mt][1] = sAl[row + 8][t];
                Al[mt][2] = sAl[row    ][t + 4];
                Al[mt][3] = sAl[row + 8][t + 4];
            }
#pragma unroll
            for (int nt = 0; nt < 4; nt++) {
                int n = wn * 32 + nt * 8 + g;
                Bh[nt][0] = *(const uint32_t*)&sBh[n * 18 + 2 * t];
                Bh[nt][1] = *(const uint32_t*)&sBh[n * 18 + 2 * t + 8];
                Bl[nt][0] = *(const uint32_t*)&sBl[n * 18 + 2 * t];
                Bl[nt][1] = *(const uint32_t*)&sBl[n * 18 + 2 * t + 8];
            }
#pragma unroll
            for (int mt = 0; mt < 2; mt++)
#pragma unroll
                for (int nt = 0; nt < 4; nt++) {
                    mma_bf16(acc[mt][nt], Ah[mt], Bh[nt]);
                    mma_bf16(acc[mt][nt], Ah[mt], Bl[nt]);
                    mma_bf16(acc[mt][nt], Al[mt], Bh[nt]);
                }
        }
        __syncthreads();
    }

    // ---- epilogue: bias (+ exact GELU for FFN1), scatter (FFN2) ----
    const float* bp = bias + (size_t)e * NDIM;
    const int g = lane >> 2, t = lane & 3;
#pragma unroll
    for (int mt = 0; mt < 2; mt++) {
#pragma unroll
        for (int half = 0; half < 2; half++) {
            int row = wm * 32 + mt * 16 + g + half * 8;
            if (m0 + row < M) {
                size_t drow;
                if (FFN1) drow = (size_t)(ooff + m0 + row);
                else      drow = (size_t)g_perm[ooff + m0 + row];
#pragma unroll
                for (int nt = 0; nt < 4; nt++) {
                    int col = n0 + wn * 32 + nt * 8 + 2 * t;
                    float v0 = acc[mt][nt][half * 2 + 0] + bp[col];
                    float v1 = acc[mt][nt][half * 2 + 1] + bp[col + 1];
                    if (FFN1) {
                        v0 = 0.5f * v0 * (1.f + erff(v0 * 0.7071067811865476f));
                        v1 = 0.5f * v1 * (1.f + erff(v1 * 0.7071067811865476f));
                    }
                    *(float2*)(Dst + drow * NDIM + col) = make_float2(v0, v1);
                }
            }
        }
    }
}

// ---------------- launch -----------------------------------------------------
extern "C" void kernel_launch(void* const* d_in, const int* in_sizes, int n_in,
                              void* d_out, int out_size) {
    const float* x  = (const float*)d_in[0];
    const float* Wr = (const float*)d_in[1];
    const float* br = (const float*)d_in[2];
    const float* W1 = (const float*)d_in[3];
    const float* b1 = (const float*)d_in[4];
    const float* W2 = (const float*)d_in[5];
    const float* b2 = (const float*)d_in[6];
    float* out = (float*)d_out;

    float* hbuf;
    cudaGetSymbolAddress((void**)&hbuf, g_h);

    k_zero<<<1, 32>>>();
    k_route<<<N_TOK / 8, 256>>>(x, Wr, br);      // 8 warps per block
    k_prefix<<<1, 1>>>();
    k_scatter<<<N_TOK / 256, 256>>>();
    // worst case: all tokens in one expert -> 256 M-tiles of 128 (empty tiles exit fast)
    k_gemm<DIMX, HID, true ><<<dim3(HID / 64, 256, NEXP), 256>>>(x, W1, b1, hbuf);
    k_gemm<HID, DIMX, false><<<dim3(DIMX / 64, 256, NEXP), 256>>>(hbuf, W2, b2, out);
}

// round 9
// speedup vs baseline: 1.6854x; 1.0597x over previous
#include <cuda_runtime.h>
#include <cuda_bf16.h>
#include <stdint.h>
#include <math.h>

#define N_TOK 32768
#define DIMX  512
#define HID   2048
#define NEXP  16

// ---------------- scratch (static device globals; no runtime allocation) ----
__device__ int g_leaf[N_TOK];
__device__ int g_cnt[NEXP];
__device__ int g_off[NEXP + 1];
__device__ int g_cur[NEXP];
__device__ int g_perm[N_TOK];

__device__ __nv_bfloat16 g_xh[(size_t)N_TOK * DIMX];
__device__ __nv_bfloat16 g_xl[(size_t)N_TOK * DIMX];
__device__ __nv_bfloat16 g_w1h[(size_t)NEXP * DIMX * HID];  // transposed [E][HID][DIMX]
__device__ __nv_bfloat16 g_w1l[(size_t)NEXP * DIMX * HID];
__device__ __nv_bfloat16 g_w2h[(size_t)NEXP * DIMX * HID];  // transposed [E][DIMX][HID]
__device__ __nv_bfloat16 g_w2l[(size_t)NEXP * DIMX * HID];
__device__ __nv_bfloat16 g_hh[(size_t)N_TOK * HID];
__device__ __nv_bfloat16 g_hl[(size_t)N_TOK * HID];

// ---------------- routing ---------------------------------------------------
__global__ void k_zero() {
    if (threadIdx.x < NEXP) g_cnt[threadIdx.x] = 0;
}

__global__ void k_route(const float* __restrict__ x,
                        const float* __restrict__ Wr,
                        const float* __restrict__ br) {
    int warp = (blockIdx.x * blockDim.x + threadIdx.x) >> 5;
    int lane = threadIdx.x & 31;
    const float4* xp = (const float4*)(x + (size_t)warp * DIMX);
    float4 xr[4];
#pragma unroll
    for (int j = 0; j < 4; j++) xr[j] = xp[lane + 32 * j];
    int leaf = 0;
#pragma unroll
    for (int d = 0; d < 4; d++) {
        int r = (1 << d) - 1 + leaf;
        const float4* wp = (const float4*)(Wr + (size_t)r * DIMX);
        float s = 0.f;
#pragma unroll
        for (int j = 0; j < 4; j++) {
            float4 w = wp[lane + 32 * j];
            s += xr[j].x * w.x; s += xr[j].y * w.y;
            s += xr[j].z * w.z; s += xr[j].w * w.w;
        }
#pragma unroll
        for (int o = 16; o; o >>= 1) s += __shfl_xor_sync(0xffffffffu, s, o);
        leaf = leaf * 2 + (((s + br[r]) > 0.f) ? 1 : 0);
    }
    if (lane == 0) {
        g_leaf[warp] = leaf;
        atomicAdd(&g_cnt[leaf], 1);
    }
}

__global__ void k_prefix() {
    int acc = 0;
    for (int e = 0; e < NEXP; e++) {
        g_off[e] = acc;
        g_cur[e] = acc;
        acc += g_cnt[e];
    }
    g_off[NEXP] = acc;
}

__global__ void k_scatter() {
    int n = blockIdx.x * blockDim.x + threadIdx.x;
    int pos = atomicAdd(&g_cur[g_leaf[n]], 1);
    g_perm[pos] = n;
}

// ---------------- split helpers ---------------------------------------------
__device__ __forceinline__ void splt(float v, __nv_bfloat16& h, __nv_bfloat16& l) {
    h = __float2bfloat16_rn(v);
    l = __float2bfloat16_rn(v - __bfloat162float(h));
}

// x -> hi/lo bf16 (elementwise, float4 per thread)
__global__ void k_split_x(const float* __restrict__ x,
                          __nv_bfloat16* __restrict__ xh,
                          __nv_bfloat16* __restrict__ xl) {
    size_t i = (size_t)(blockIdx.x * blockDim.x + threadIdx.x) * 4;
    float4 v = *(const float4*)(x + i);
    __nv_bfloat162 h01, h23, l01, l23;
    splt(v.x, h01.x, l01.x); splt(v.y, h01.y, l01.y);
    splt(v.z, h23.x, l23.x); splt(v.w, h23.y, l23.y);
    *(__nv_bfloat162*)(xh + i)     = h01;
    *(__nv_bfloat162*)(xh + i + 2) = h23;
    *(__nv_bfloat162*)(xl + i)     = l01;
    *(__nv_bfloat162*)(xl + i + 2) = l23;
}

// W [E][K][N] -> transposed hi/lo [E][N][K]  (32x32 smem tiles)
__global__ void k_split_wT(const float* __restrict__ W,
                           __nv_bfloat16* __restrict__ Th,
                           __nv_bfloat16* __restrict__ Tl,
                           int K, int N) {
    __shared__ float s[32][33];
    int e  = blockIdx.z;
    int k0 = blockIdx.y * 32;
    int n0 = blockIdx.x * 32;
    int tx = threadIdx.x, ty = threadIdx.y;
    const float* Wp = W + (size_t)e * K * N;
#pragma unroll
    for (int i = 0; i < 4; i++)
        s[ty + i * 8][tx] = Wp[(size_t)(k0 + ty + i * 8) * N + n0 + tx];
    __syncthreads();
    __nv_bfloat16* ThP = Th + (size_t)e * N * K;
    __nv_bfloat16* TlP = Tl + (size_t)e * N * K;
#pragma unroll
    for (int i = 0; i < 4; i++) {
        int rn = ty + i * 8;
        float v = s[tx][rn];
        __nv_bfloat16 h, l;
        splt(v, h, l);
        ThP[(size_t)(n0 + rn) * K + k0 + tx] = h;
        TlP[(size_t)(n0 + rn) * K + k0 + tx] = l;
    }
}

// ---------------- mma + cp.async helpers ------------------------------------
__device__ __forceinline__ void mma_bf16(float* c, const uint32_t* a, const uint32_t* b) {
    asm volatile(
        "mma.sync.aligned.m16n8k16.row.col.f32.bf16.bf16.f32 "
        "{%0,%1,%2,%3}, {%4,%5,%6,%7}, {%8,%9}, {%0,%1,%2,%3};"
        : "+f"(c[0]), "+f"(c[1]), "+f"(c[2]), "+f"(c[3])
        : "r"(a[0]), "r"(a[1]), "r"(a[2]), "r"(a[3]), "r"(b[0]), "r"(b[1]));
}

__device__ __forceinline__ void cp16(void* smem_dst, const void* gmem_src) {
    uint32_t s = (uint32_t)__cvta_generic_to_shared(smem_dst);
    asm volatile("cp.async.cg.shared.global [%0], [%1], 16;" :: "r"(s), "l"(gmem_src));
}

// ---------------- grouped GEMM (pre-split bf16, cp.async double-buffered) ----
// Tile: BM=128, BN=64, BK=32. 8 warps (4M x 2N), warp 32x32, 3-product split.
// smem rows padded to 40 bf16 (20 u32 words) -> conflict-free fragment LDS.
// Dynamic smem: sA[2 stages][hi/lo][128*40], sB[2][2][64*40] = 61440 bytes.
template<int KDIM, int NDIM, bool FFN1>
__global__ __launch_bounds__(256, 2)
void k_gemm(const __nv_bfloat16* __restrict__ Ah_g, const __nv_bfloat16* __restrict__ Al_g,
            const __nv_bfloat16* __restrict__ Bh_g, const __nv_bfloat16* __restrict__ Bl_g,
            const float* __restrict__ bias,
            __nv_bfloat16* __restrict__ Dh, __nv_bfloat16* __restrict__ Dl,
            float* __restrict__ Dout) {
    const int e  = blockIdx.z;
    const int M  = g_cnt[e];
    const int m0 = blockIdx.y * 128;
    if (m0 >= M) return;
    const int n0   = blockIdx.x * 64;
    const int tid  = threadIdx.x;
    const int lane = tid & 31;
    const int wm   = (tid >> 5) >> 1;
    const int wn   = (tid >> 5) & 1;
    const int ooff = g_off[e];

    extern __shared__ char smraw[];
    __nv_bfloat16* smA = (__nv_bfloat16*)smraw;                 // 4 * 5120 elems
    __nv_bfloat16* smB = (__nv_bfloat16*)(smraw + 40960);       // 4 * 2560 elems

    // ---- producer mappings ----
    const int arow  = tid >> 1;          // 0..127
    const int ahalf = tid & 1;           // 2 x 16B chunks each (per hi/lo)
    const bool aval = (m0 + arow) < M;
    size_t arow_idx;
    if (FFN1) arow_idx = (size_t)(aval ? g_perm[ooff + m0 + arow] : 0);
    else      arow_idx = (size_t)(aval ? (ooff + m0 + arow) : 0);
    const __nv_bfloat16* aph = Ah_g + arow_idx * KDIM;
    const __nv_bfloat16* apl = Al_g + arow_idx * KDIM;

    const int bn = tid >> 2;             // 0..63
    const int bc = tid & 3;              // chunk 0..3
    const __nv_bfloat16* bph = Bh_g + ((size_t)e * NDIM + n0 + bn) * KDIM;
    const __nv_bfloat16* bpl = Bl_g + ((size_t)e * NDIM + n0 + bn) * KDIM;

    auto load_stage = [&](int s, int ke) {
#pragma unroll
        for (int c = 0; c < 2; c++) {
            int off = (ahalf * 2 + c) * 8;
            cp16(smA + (s * 2 + 0) * 5120 + arow * 40 + off, aph + ke + off);
            cp16(smA + (s * 2 + 1) * 5120 + arow * 40 + off, apl + ke + off);
        }
        {
            int off = bc * 8;
            cp16(smB + (s * 2 + 0) * 2560 + bn * 40 + off, bph + ke + off);
            cp16(smB + (s * 2 + 1) * 2560 + bn * 40 + off, bpl + ke + off);
        }
        asm volatile("cp.async.commit_group;");
    };

    float acc[2][4][4];
#pragma unroll
    for (int mt = 0; mt < 2; mt++)
#pragma unroll
        for (int nt = 0; nt < 4; nt++)
#pragma unroll
            for (int i = 0; i < 4; i++) acc[mt][nt][i] = 0.f;

    constexpr int NCH = KDIM / 32;
    load_stage(0, 0);
    load_stage(1, 32);

    const int gl = lane >> 2, tl = lane & 3;

    for (int ch = 0; ch < NCH; ch++) {
        const int s = ch & 1;
        if (ch < NCH - 2) asm volatile("cp.async.wait_group 1;");
        else              asm volatile("cp.async.wait_group 0;");
        __syncthreads();

        const uint32_t* A_h = (const uint32_t*)(smA + (s * 2 + 0) * 5120);
        const uint32_t* A_l = (const uint32_t*)(smA + (s * 2 + 1) * 5120);
        const uint32_t* B_h = (const uint32_t*)(smB + (s * 2 + 0) * 2560);
        const uint32_t* B_l = (const uint32_t*)(smB + (s * 2 + 1) * 2560);

#pragma unroll
        for (int ks = 0; ks < 2; ks++) {
            const int wb = ks * 8;
            uint32_t Ah[2][4], Al[2][4], Bh[4][2], Bl[4][2];
#pragma unroll
            for (int mt = 0; mt < 2; mt++) {
                int r0 = wm * 32 + mt * 16 + gl;
                Ah[mt][0] = A_h[r0 * 20 + wb + tl];
                Ah[mt][1] = A_h[(r0 + 8) * 20 + wb + tl];
                Ah[mt][2] = A_h[r0 * 20 + wb + tl + 4];
                Ah[mt][3] = A_h[(r0 + 8) * 20 + wb + tl + 4];
                Al[mt][0] = A_l[r0 * 20 + wb + tl];
                Al[mt][1] = A_l[(r0 + 8) * 20 + wb + tl];
                Al[mt][2] = A_l[r0 * 20 + wb + tl + 4];
                Al[mt][3] = A_l[(r0 + 8) * 20 + wb + tl + 4];
            }
#pragma unroll
            for (int nt = 0; nt < 4; nt++) {
                int n = wn * 32 + nt * 8 + gl;
                Bh[nt][0] = B_h[n * 20 + wb + tl];
                Bh[nt][1] = B_h[n * 20 + wb + tl + 4];
                Bl[nt][0] = B_l[n * 20 + wb + tl];
                Bl[nt][1] = B_l[n * 20 + wb + tl + 4];
            }
#pragma unroll
            for (int mt = 0; mt < 2; mt++)
#pragma unroll
                for (int nt = 0; nt < 4; nt++) {
                    mma_bf16(acc[mt][nt], Ah[mt], Bh[nt]);
                    mma_bf16(acc[mt][nt], Ah[mt], Bl[nt]);
                    mma_bf16(acc[mt][nt], Al[mt], Bh[nt]);
                }
        }
        __syncthreads();
        if (ch + 2 < NCH) load_stage(s, (ch + 2) * 32);
    }

    // ---- epilogue ----
    const float* bp = bias + (size_t)e * NDIM;
#pragma unroll
    for (int mt = 0; mt < 2; mt++) {
#pragma unroll
        for (int half = 0; half < 2; half++) {
            int row = wm * 32 + mt * 16 + gl + half * 8;
            if (m0 + row < M) {
#pragma unroll
                for (int nt = 0; nt < 4; nt++) {
                    int col = n0 + wn * 32 + nt * 8 + 2 * tl;
                    float v0 = acc[mt][nt][half * 2 + 0] + bp[col];
                    float v1 = acc[mt][nt][half * 2 + 1] + bp[col + 1];
                    if (FFN1) {
                        v0 = 0.5f * v0 * (1.f + erff(v0 * 0.7071067811865476f));
                        v1 = 0.5f * v1 * (1.f + erff(v1 * 0.7071067811865476f));
                        size_t drow = (size_t)(ooff + m0 + row);
                        __nv_bfloat162 H, L;
                        splt(v0, H.x, L.x);
                        splt(v1, H.y, L.y);
                        *(__nv_bfloat162*)(Dh + drow * NDIM + col) = H;
                        *(__nv_bfloat162*)(Dl + drow * NDIM + col) = L;
                    } else {
                        size_t drow = (size_t)g_perm[ooff + m0 + row];
                        *(float2*)(Dout + drow * NDIM + col) = make_float2(v0, v1);
                    }
                }
            }
        }
    }
}

// ---------------- launch -----------------------------------------------------
extern "C" void kernel_launch(void* const* d_in, const int* in_sizes, int n_in,
                              void* d_out, int out_size) {
    const float* x  = (const float*)d_in[0];
    const float* Wr = (const float*)d_in[1];
    const float* br = (const float*)d_in[2];
    const float* W1 = (const float*)d_in[3];
    const float* b1 = (const float*)d_in[4];
    const float* W2 = (const float*)d_in[5];
    const float* b2 = (const float*)d_in[6];
    float* out = (float*)d_out;

    __nv_bfloat16 *xh, *xl, *w1h, *w1l, *w2h, *w2l, *hh, *hl;
    cudaGetSymbolAddress((void**)&xh,  g_xh);
    cudaGetSymbolAddress((void**)&xl,  g_xl);
    cudaGetSymbolAddress((void**)&w1h, g_w1h);
    cudaGetSymbolAddress((void**)&w1l, g_w1l);
    cudaGetSymbolAddress((void**)&w2h, g_w2h);
    cudaGetSymbolAddress((void**)&w2l, g_w2l);
    cudaGetSymbolAddress((void**)&hh,  g_hh);
    cudaGetSymbolAddress((void**)&hl,  g_hl);

    // host-side attribute set (not stream-captured); call every time, no guards
    cudaFuncSetAttribute(k_gemm<DIMX, HID, true>,
                         cudaFuncAttributeMaxDynamicSharedMemorySize, 61440);
    cudaFuncSetAttribute(k_gemm<HID, DIMX, false>,
                         cudaFuncAttributeMaxDynamicSharedMemorySize, 61440);

    k_zero<<<1, 32>>>();
    k_route<<<N_TOK / 8, 256>>>(x, Wr, br);
    k_prefix<<<1, 1>>>();
    k_scatter<<<N_TOK / 256, 256>>>();

    k_split_x<<<(N_TOK * DIMX / 4) / 256, 256>>>(x, xh, xl);
    k_split_wT<<<dim3(HID / 32, DIMX / 32, NEXP), dim3(32, 8)>>>(W1, w1h, w1l, DIMX, HID);
    k_split_wT<<<dim3(DIMX / 32, HID / 32, NEXP), dim3(32, 8)>>>(W2, w2h, w2l, HID, DIMX);

    // worst case: all tokens in one expert -> 256 M-tiles (empty tiles exit fast)
    k_gemm<DIMX, HID, true ><<<dim3(HID / 64, 256, NEXP), 256, 61440>>>(
        xh, xl, w1h, w1l, b1, hh, hl, nullptr);
    k_gemm<HID, DIMX, false><<<dim3(DIMX / 64, 256, NEXP), 256, 61440>>>(
        hh, hl, w2h, w2l, b2, nullptr, nullptr, out);
}

// round 11
// speedup vs baseline: 2.0255x; 1.2018x over previous
#include <cuda_runtime.h>
#include <cuda_fp16.h>
#include <stdint.h>
#include <math.h>

#define N_TOK 32768
#define DIMX  512
#define HID   2048
#define NEXP  16

// ---------------- scratch (static device globals; no runtime allocation) ----
__device__ int g_leaf[N_TOK];
__device__ int g_cnt[NEXP];
__device__ int g_off[NEXP + 1];
__device__ int g_cur[NEXP];
__device__ int g_perm[N_TOK];

__device__ __half g_xh[(size_t)N_TOK * DIMX];
__device__ __half g_xl[(size_t)N_TOK * DIMX];
__device__ __half g_w1h[(size_t)NEXP * DIMX * HID];  // transposed [E][HID][DIMX], hi only
__device__ __half g_w2h[(size_t)NEXP * DIMX * HID];  // transposed [E][DIMX][HID], hi only
__device__ __half g_hh[(size_t)N_TOK * HID];
__device__ __half g_hl[(size_t)N_TOK * HID];

// ---------------- routing ---------------------------------------------------
__global__ void k_zero() {
    if (threadIdx.x < NEXP) g_cnt[threadIdx.x] = 0;
}

__global__ void k_route(const float* __restrict__ x,
                        const float* __restrict__ Wr,
                        const float* __restrict__ br) {
    int warp = (blockIdx.x * blockDim.x + threadIdx.x) >> 5;
    int lane = threadIdx.x & 31;
    const float4* xp = (const float4*)(x + (size_t)warp * DIMX);
    float4 xr[4];
#pragma unroll
    for (int j = 0; j < 4; j++) xr[j] = xp[lane + 32 * j];
    int leaf = 0;
#pragma unroll
    for (int d = 0; d < 4; d++) {
        int r = (1 << d) - 1 + leaf;
        const float4* wp = (const float4*)(Wr + (size_t)r * DIMX);
        float s = 0.f;
#pragma unroll
        for (int j = 0; j < 4; j++) {
            float4 w = wp[lane + 32 * j];
            s += xr[j].x * w.x; s += xr[j].y * w.y;
            s += xr[j].z * w.z; s += xr[j].w * w.w;
        }
#pragma unroll
        for (int o = 16; o; o >>= 1) s += __shfl_xor_sync(0xffffffffu, s, o);
        leaf = leaf * 2 + (((s + br[r]) > 0.f) ? 1 : 0);
    }
    if (lane == 0) {
        g_leaf[warp] = leaf;
        atomicAdd(&g_cnt[leaf], 1);
    }
}

__global__ void k_prefix() {
    int acc = 0;
    for (int e = 0; e < NEXP; e++) {
        g_off[e] = acc;
        g_cur[e] = acc;
        acc += g_cnt[e];
    }
    g_off[NEXP] = acc;
}

__global__ void k_scatter() {
    int n = blockIdx.x * blockDim.x + threadIdx.x;
    int pos = atomicAdd(&g_cur[g_leaf[n]], 1);
    g_perm[pos] = n;
}

// ---------------- split helpers (fp16 hi/lo) ---------------------------------
__device__ __forceinline__ void splt(float v, __half& h, __half& l) {
    h = __float2half_rn(v);
    l = __float2half_rn(v - __half2float(h));
}

// x -> fp16 hi/lo
__global__ void k_split_x(const float* __restrict__ x,
                          __half* __restrict__ xh,
                          __half* __restrict__ xl) {
    size_t i = (size_t)(blockIdx.x * blockDim.x + threadIdx.x) * 4;
    float4 v = *(const float4*)(x + i);
    __half2 h01, h23, l01, l23;
    splt(v.x, h01.x, l01.x); splt(v.y, h01.y, l01.y);
    splt(v.z, h23.x, l23.x); splt(v.w, h23.y, l23.y);
    *(__half2*)(xh + i)     = h01;
    *(__half2*)(xh + i + 2) = h23;
    *(__half2*)(xl + i)     = l01;
    *(__half2*)(xl + i + 2) = l23;
}

// W [E][K][N] -> transposed fp16 hi [E][N][K]
__global__ void k_split_wT(const float* __restrict__ W,
                           __half* __restrict__ Th,
                           int K, int N) {
    __shared__ float s[32][33];
    int e  = blockIdx.z;
    int k0 = blockIdx.y * 32;
    int n0 = blockIdx.x * 32;
    int tx = threadIdx.x, ty = threadIdx.y;
    const float* Wp = W + (size_t)e * K * N;
#pragma unroll
    for (int i = 0; i < 4; i++)
        s[ty + i * 8][tx] = Wp[(size_t)(k0 + ty + i * 8) * N + n0 + tx];
    __syncthreads();
    __half* ThP = Th + (size_t)e * N * K;
#pragma unroll
    for (int i = 0; i < 4; i++) {
        int rn = ty + i * 8;
        ThP[(size_t)(n0 + rn) * K + k0 + tx] = __float2half_rn(s[tx][rn]);
    }
}

// ---------------- mma + cp.async helpers ------------------------------------
__device__ __forceinline__ void mma_f16(float* c, const uint32_t* a, const uint32_t* b) {
    asm volatile(
        "mma.sync.aligned.m16n8k16.row.col.f32.f16.f16.f32 "
        "{%0,%1,%2,%3}, {%4,%5,%6,%7}, {%8,%9}, {%0,%1,%2,%3};"
        : "+f"(c[0]), "+f"(c[1]), "+f"(c[2]), "+f"(c[3])
        : "r"(a[0]), "r"(a[1]), "r"(a[2]), "r"(a[3]), "r"(b[0]), "r"(b[1]));
}

__device__ __forceinline__ void cp16(void* smem_dst, const void* gmem_src) {
    uint32_t s = (uint32_t)__cvta_generic_to_shared(smem_dst);
    asm volatile("cp.async.cg.shared.global [%0], [%1], 16;" :: "r"(s), "l"(gmem_src));
}

// ---------------- grouped GEMM (fp16 2-product split) ------------------------
// D = (Ah + Al) @ Bh^T : tile BM=128, BN=64, BK=32, 8 warps (4M x 2N), warp 32x32.
// smem rows padded to 40 halves (20 u32 words) -> conflict-free fragment LDS.
// Dynamic smem: sA[2 stages][hi/lo][128*40] + sB[2][64*40] = 51200 bytes.
template<int KDIM, int NDIM, bool FFN1>
__global__ __launch_bounds__(256, 2)
void k_gemm(const __half* __restrict__ Ah_g, const __half* __restrict__ Al_g,
            const __half* __restrict__ Bh_g,
            const float* __restrict__ bias,
            __half* __restrict__ Dh, __half* __restrict__ Dl,
            float* __restrict__ Dout) {
    const int e  = blockIdx.z;
    const int M  = g_cnt[e];
    const int m0 = blockIdx.y * 128;
    if (m0 >= M) return;
    const int n0   = blockIdx.x * 64;
    const int tid  = threadIdx.x;
    const int lane = tid & 31;
    const int wm   = (tid >> 5) >> 1;
    const int wn   = (tid >> 5) & 1;
    const int ooff = g_off[e];

    extern __shared__ char smraw[];
    __half* smA = (__half*)smraw;                 // [2 stages][2 hl] * 5120 elems
    __half* smB = (__half*)(smraw + 40960);       // [2 stages] * 2560 elems

    // ---- producer mappings ----
    const int arow  = tid >> 1;          // 0..127
    const int ahalf = tid & 1;           // 2 x 16B chunks each (per hi/lo)
    const bool aval = (m0 + arow) < M;
    size_t arow_idx;
    if (FFN1) arow_idx = (size_t)(aval ? g_perm[ooff + m0 + arow] : 0);
    else      arow_idx = (size_t)(aval ? (ooff + m0 + arow) : 0);
    const __half* aph = Ah_g + arow_idx * KDIM;
    const __half* apl = Al_g + arow_idx * KDIM;

    const int bn = tid >> 2;             // 0..63
    const int bc = tid & 3;              // chunk 0..3
    const __half* bph = Bh_g + ((size_t)e * NDIM + n0 + bn) * KDIM;

    auto load_stage = [&](int s, int ke) {
#pragma unroll
        for (int c = 0; c < 2; c++) {
            int off = (ahalf * 2 + c) * 8;
            cp16(smA + (s * 2 + 0) * 5120 + arow * 40 + off, aph + ke + off);
            cp16(smA + (s * 2 + 1) * 5120 + arow * 40 + off, apl + ke + off);
        }
        cp16(smB + s * 2560 + bn * 40 + bc * 8, bph + ke + bc * 8);
        asm volatile("cp.async.commit_group;");
    };

    float acc[2][4][4];
#pragma unroll
    for (int mt = 0; mt < 2; mt++)
#pragma unroll
        for (int nt = 0; nt < 4; nt++)
#pragma unroll
            for (int i = 0; i < 4; i++) acc[mt][nt][i] = 0.f;

    constexpr int NCH = KDIM / 32;
    load_stage(0, 0);
    load_stage(1, 32);

    const int gl = lane >> 2, tl = lane & 3;

    for (int ch = 0; ch < NCH; ch++) {
        const int s = ch & 1;
        if (ch < NCH - 2) asm volatile("cp.async.wait_group 1;");
        else              asm volatile("cp.async.wait_group 0;");
        __syncthreads();

        const uint32_t* A_h = (const uint32_t*)(smA + (s * 2 + 0) * 5120);
        const uint32_t* A_l = (const uint32_t*)(smA + (s * 2 + 1) * 5120);
        const uint32_t* B_h = (const uint32_t*)(smB + s * 2560);

#pragma unroll
        for (int ks = 0; ks < 2; ks++) {
            const int wb = ks * 8;
            uint32_t Ah[2][4], Al[2][4], Bh[4][2];
#pragma unroll
            for (int mt = 0; mt < 2; mt++) {
                int r0 = wm * 32 + mt * 16 + gl;
                Ah[mt][0] = A_h[r0 * 20 + wb + tl];
                Ah[mt][1] = A_h[(r0 + 8) * 20 + wb + tl];
                Ah[mt][2] = A_h[r0 * 20 + wb + tl + 4];
                Ah[mt][3] = A_h[(r0 + 8) * 20 + wb + tl + 4];
                Al[mt][0] = A_l[r0 * 20 + wb + tl];
                Al[mt][1] = A_l[(r0 + 8) * 20 + wb + tl];
                Al[mt][2] = A_l[r0 * 20 + wb + tl + 4];
                Al[mt][3] = A_l[(r0 + 8) * 20 + wb + tl + 4];
            }
#pragma unroll
            for (int nt = 0; nt < 4; nt++) {
                int n = wn * 32 + nt * 8 + gl;
                Bh[nt][0] = B_h[n * 20 + wb + tl];
                Bh[nt][1] = B_h[n * 20 + wb + tl + 4];
            }
#pragma unroll
            for (int mt = 0; mt < 2; mt++)
#pragma unroll
                for (int nt = 0; nt < 4; nt++) {
                    mma_f16(acc[mt][nt], Ah[mt], Bh[nt]);
                    mma_f16(acc[mt][nt], Al[mt], Bh[nt]);
                }
        }
        __syncthreads();
        if (ch + 2 < NCH) load_stage(s, (ch + 2) * 32);
    }

    // ---- epilogue ----
    const float* bp = bias + (size_t)e * NDIM;
#pragma unroll
    for (int mt = 0; mt < 2; mt++) {
#pragma unroll
        for (int half = 0; half < 2; half++) {
            int row = wm * 32 + mt * 16 + gl + half * 8;
            if (m0 + row < M) {
#pragma unroll
                for (int nt = 0; nt < 4; nt++) {
                    int col = n0 + wn * 32 + nt * 8 + 2 * tl;
                    float v0 = acc[mt][nt][half * 2 + 0] + bp[col];
                    float v1 = acc[mt][nt][half * 2 + 1] + bp[col + 1];
                    if (FFN1) {
                        v0 = 0.5f * v0 * (1.f + erff(v0 * 0.7071067811865476f));
                        v1 = 0.5f * v1 * (1.f + erff(v1 * 0.7071067811865476f));
                        size_t drow = (size_t)(ooff + m0 + row);
                        __half2 H, L;
                        splt(v0, H.x, L.x);
                        splt(v1, H.y, L.y);
                        *(__half2*)(Dh + drow * NDIM + col) = H;
                        *(__half2*)(Dl + drow * NDIM + col) = L;
                    } else {
                        size_t drow = (size_t)g_perm[ooff + m0 + row];
                        *(float2*)(Dout + drow * NDIM + col) = make_float2(v0, v1);
                    }
                }
            }
        }
    }
}

// ---------------- launch -----------------------------------------------------
#define GEMM_SMEM 51200

extern "C" void kernel_launch(void* const* d_in, const int* in_sizes, int n_in,
                              void* d_out, int out_size) {
    const float* x  = (const float*)d_in[0];
    const float* Wr = (const float*)d_in[1];
    const float* br = (const float*)d_in[2];
    const float* W1 = (const float*)d_in[3];
    const float* b1 = (const float*)d_in[4];
    const float* W2 = (const float*)d_in[5];
    const float* b2 = (const float*)d_in[6];
    float* out = (float*)d_out;

    __half *xh, *xl, *w1h, *w2h, *hh, *hl;
    cudaGetSymbolAddress((void**)&xh,  g_xh);
    cudaGetSymbolAddress((void**)&xl,  g_xl);
    cudaGetSymbolAddress((void**)&w1h, g_w1h);
    cudaGetSymbolAddress((void**)&w2h, g_w2h);
    cudaGetSymbolAddress((void**)&hh,  g_hh);
    cudaGetSymbolAddress((void**)&hl,  g_hl);

    // host-side attribute set (not stream-captured); call every time, no guards
    cudaFuncSetAttribute(k_gemm<DIMX, HID, true>,
                         cudaFuncAttributeMaxDynamicSharedMemorySize, GEMM_SMEM);
    cudaFuncSetAttribute(k_gemm<HID, DIMX, false>,
                         cudaFuncAttributeMaxDynamicSharedMemorySize, GEMM_SMEM);

    k_zero<<<1, 32>>>();
    k_route<<<N_TOK / 8, 256>>>(x, Wr, br);
    k_prefix<<<1, 1>>>();
    k_scatter<<<N_TOK / 256, 256>>>();

    k_split_x<<<(N_TOK * DIMX / 4) / 256, 256>>>(x, xh, xl);
    k_split_wT<<<dim3(HID / 32, DIMX / 32, NEXP), dim3(32, 8)>>>(W1, w1h, DIMX, HID);
    k_split_wT<<<dim3(DIMX / 32, HID / 32, NEXP), dim3(32, 8)>>>(W2, w2h, HID, DIMX);

    // worst case: all tokens in one expert -> 256 M-tiles (empty tiles exit fast)
    k_gemm<DIMX, HID, true ><<<dim3(HID / 64, 256, NEXP), 256, GEMM_SMEM>>>(
        xh, xl, w1h, b1, hh, hl, nullptr);
    k_gemm<HID, DIMX, false><<<dim3(DIMX / 64, 256, NEXP), 256, GEMM_SMEM>>>(
        hh, hl, w2h, b2, nullptr, nullptr, out);
}

// round 13
// speedup vs baseline: 2.0467x; 1.0104x over previous
#include <cuda_runtime.h>
#include <cuda_fp16.h>
#include <stdint.h>
#include <math.h>

#define N_TOK 32768
#define DIMX  512
#define HID   2048
#define NEXP  16
#define MAXTILE 272   // sum ceil(Me/128) <= 256 + 16

// ---------------- scratch (static device globals; no runtime allocation) ----
__device__ int g_leaf[N_TOK];
__device__ int g_cnt[NEXP];
__device__ int g_off[NEXP + 1];
__device__ int g_cur[NEXP];
__device__ int g_perm[N_TOK];
__device__ int g_tmap_e[MAXTILE];
__device__ int g_tmap_m[MAXTILE];
__device__ int g_ntile;

__device__ __half g_xh[(size_t)N_TOK * DIMX];
__device__ __half g_xl[(size_t)N_TOK * DIMX];
__device__ __half g_w1h[(size_t)NEXP * DIMX * HID];  // transposed [E][HID][DIMX]
__device__ __half g_w2h[(size_t)NEXP * DIMX * HID];  // transposed [E][DIMX][HID]
__device__ __half g_hh[(size_t)N_TOK * HID];
__device__ __half g_hl[(size_t)N_TOK * HID];

// ---------------- routing ---------------------------------------------------
__global__ void k_zero() {
    if (threadIdx.x < NEXP) g_cnt[threadIdx.x] = 0;
}

__global__ void k_route(const float* __restrict__ x,
                        const float* __restrict__ Wr,
                        const float* __restrict__ br) {
    int warp = (blockIdx.x * blockDim.x + threadIdx.x) >> 5;
    int lane = threadIdx.x & 31;
    const float4* xp = (const float4*)(x + (size_t)warp * DIMX);
    float4 xr[4];
#pragma unroll
    for (int j = 0; j < 4; j++) xr[j] = xp[lane + 32 * j];
    int leaf = 0;
#pragma unroll
    for (int d = 0; d < 4; d++) {
        int r = (1 << d) - 1 + leaf;
        const float4* wp = (const float4*)(Wr + (size_t)r * DIMX);
        float s = 0.f;
#pragma unroll
        for (int j = 0; j < 4; j++) {
            float4 w = wp[lane + 32 * j];
            s += xr[j].x * w.x; s += xr[j].y * w.y;
            s += xr[j].z * w.z; s += xr[j].w * w.w;
        }
#pragma unroll
        for (int o = 16; o; o >>= 1) s += __shfl_xor_sync(0xffffffffu, s, o);
        leaf = leaf * 2 + (((s + br[r]) > 0.f) ? 1 : 0);
    }
    if (lane == 0) {
        g_leaf[warp] = leaf;
        atomicAdd(&g_cnt[leaf], 1);
    }
}

// prefix + tile map (sum of ceil(Me/128) tiles, no empty-expert fat)
__global__ void k_prefix() {
    int acc = 0, t = 0;
    for (int e = 0; e < NEXP; e++) {
        g_off[e] = acc;
        g_cur[e] = acc;
        int c = g_cnt[e];
        for (int m = 0; m < c; m += 128) {
            g_tmap_e[t] = e;
            g_tmap_m[t] = m;
            t++;
        }
        acc += c;
    }
    g_off[NEXP] = acc;
    g_ntile = t;
    for (int i = t; i < MAXTILE; i++) { g_tmap_e[i] = -1; g_tmap_m[i] = 0; }
}

__global__ void k_scatter() {
    int n = blockIdx.x * blockDim.x + threadIdx.x;
    int pos = atomicAdd(&g_cur[g_leaf[n]], 1);
    g_perm[pos] = n;
}

// ---------------- split helpers (fp16 hi/lo) ---------------------------------
__device__ __forceinline__ void splt(float v, __half& h, __half& l) {
    h = __float2half_rn(v);
    l = __float2half_rn(v - __half2float(h));
}

__global__ void k_split_x(const float* __restrict__ x,
                          __half* __restrict__ xh,
                          __half* __restrict__ xl) {
    size_t i = (size_t)(blockIdx.x * blockDim.x + threadIdx.x) * 4;
    float4 v = *(const float4*)(x + i);
    __half2 h01, h23, l01, l23;
    splt(v.x, h01.x, l01.x); splt(v.y, h01.y, l01.y);
    splt(v.z, h23.x, l23.x); splt(v.w, h23.y, l23.y);
    *(__half2*)(xh + i)     = h01;
    *(__half2*)(xh + i + 2) = h23;
    *(__half2*)(xl + i)     = l01;
    *(__half2*)(xl + i + 2) = l23;
}

// W [E][K][N] -> transposed fp16 hi [E][N][K]
__global__ void k_split_wT(const float* __restrict__ W,
                           __half* __restrict__ Th,
                           int K, int N) {
    __shared__ float s[32][33];
    int e  = blockIdx.z;
    int k0 = blockIdx.y * 32;
    int n0 = blockIdx.x * 32;
    int tx = threadIdx.x, ty = threadIdx.y;
    const float* Wp = W + (size_t)e * K * N;
#pragma unroll
    for (int i = 0; i < 4; i++)
        s[ty + i * 8][tx] = Wp[(size_t)(k0 + ty + i * 8) * N + n0 + tx];
    __syncthreads();
    __half* ThP = Th + (size_t)e * N * K;
#pragma unroll
    for (int i = 0; i < 4; i++) {
        int rn = ty + i * 8;
        ThP[(size_t)(n0 + rn) * K + k0 + tx] = __float2half_rn(s[tx][rn]);
    }
}

// ---------------- mma / ldmatrix / cp.async ----------------------------------
__device__ __forceinline__ void mma_f16(float* c, const uint32_t* a, const uint32_t* b) {
    asm volatile(
        "mma.sync.aligned.m16n8k16.row.col.f32.f16.f16.f32 "
        "{%0,%1,%2,%3}, {%4,%5,%6,%7}, {%8,%9}, {%0,%1,%2,%3};"
        : "+f"(c[0]), "+f"(c[1]), "+f"(c[2]), "+f"(c[3])
        : "r"(a[0]), "r"(a[1]), "r"(a[2]), "r"(a[3]), "r"(b[0]), "r"(b[1]));
}

__device__ __forceinline__ void ldm_x4(uint32_t* r, uint32_t addr) {
    asm volatile("ldmatrix.sync.aligned.m8n8.x4.shared.b16 {%0,%1,%2,%3}, [%4];"
                 : "=r"(r[0]), "=r"(r[1]), "=r"(r[2]), "=r"(r[3]) : "r"(addr));
}

__device__ __forceinline__ void cp16(uint32_t smem_dst, const void* gmem_src) {
    asm volatile("cp.async.cg.shared.global [%0], [%1], 16;" :: "r"(smem_dst), "l"(gmem_src));
}

// ---------------- grouped GEMM (fp16 2-product, ldmatrix, BK=64) -------------
// D = (Ah + Al) @ Bh^T. Tile BM=128, BN=64, BK=64; 8 warps (4M x 2N), warp 32x32.
// smem rows: 72 halves (144B) -> ldmatrix phase-conflict-free (+4 banks/row).
// Dyn smem: sA[2 stg][hi/lo][128*72] + sB[2][64*72] halves = 92160 bytes.
#define ROWP 72
#define A_ST (128 * ROWP)           // halves per A tile
#define B_ST (64 * ROWP)
template<int KDIM, int NDIM, bool FFN1>
__global__ __launch_bounds__(256, 2)
void k_gemm(const __half* __restrict__ Ah_g, const __half* __restrict__ Al_g,
            const __half* __restrict__ Bh_g,
            const float* __restrict__ bias,
            __half* __restrict__ Dh, __half* __restrict__ Dl,
            float* __restrict__ Dout) {
    const int t = blockIdx.y;
    const int e = g_tmap_e[t];
    if (e < 0) return;
    const int M    = g_cnt[e];
    const int m0   = g_tmap_m[t];
    const int n0   = blockIdx.x * 64;
    const int tid  = threadIdx.x;
    const int lane = tid & 31;
    const int wm   = (tid >> 5) >> 1;
    const int wn   = (tid >> 5) & 1;
    const int ooff = g_off[e];

    extern __shared__ __half sm[];
    const uint32_t smb = (uint32_t)__cvta_generic_to_shared(sm);
    // layout (halves): [0]=Ah s0, [1]=Al s0, [2]=Ah s1, [3]=Al s1, then B s0, B s1
    const uint32_t aOff[4] = {smb, smb + A_ST * 2, smb + 2 * A_ST * 2, smb + 3 * A_ST * 2};
    const uint32_t bOff[2] = {smb + 4 * A_ST * 2, smb + 4 * A_ST * 2 + B_ST * 2};

    // ---- producers ----
    const int arow = tid >> 1;           // 0..127
    const int ac0  = (tid & 1) * 4;      // 4 x 16B chunks (per hi/lo)
    const bool aval = (m0 + arow) < M;
    size_t arow_idx;
    if (FFN1) arow_idx = (size_t)(aval ? g_perm[ooff + m0 + arow] : 0);
    else      arow_idx = (size_t)(aval ? (ooff + m0 + arow) : 0);
    const __half* aph = Ah_g + arow_idx * KDIM;
    const __half* apl = Al_g + arow_idx * KDIM;

    const int brow = tid >> 2;           // 0..63
    const int bc0  = (tid & 3) * 2;      // 2 x 16B chunks
    const __half* bph = Bh_g + ((size_t)e * NDIM + n0 + brow) * KDIM;

    auto load_stage = [&](int s, int ke) {
        const uint32_t da = arow * ROWP * 2;
#pragma unroll
        for (int c = 0; c < 4; c++) {
            cp16(aOff[s * 2 + 0] + da + (ac0 + c) * 16, aph + ke + (ac0 + c) * 8);
            cp16(aOff[s * 2 + 1] + da + (ac0 + c) * 16, apl + ke + (ac0 + c) * 8);
        }
        const uint32_t db = brow * ROWP * 2;
        cp16(bOff[s] + db + (bc0 + 0) * 16, bph + ke + (bc0 + 0) * 8);
        cp16(bOff[s] + db + (bc0 + 1) * 16, bph + ke + (bc0 + 1) * 8);
        asm volatile("cp.async.commit_group;");
    };

    float acc[2][4][4];
#pragma unroll
    for (int mt = 0; mt < 2; mt++)
#pragma unroll
        for (int nt = 0; nt < 4; nt++)
#pragma unroll
            for (int i = 0; i < 4; i++) acc[mt][nt][i] = 0.f;

    constexpr int NCH = KDIM / 64;
    load_stage(0, 0);
    if (NCH > 1) load_stage(1, 64);

    // ldmatrix lane geometry (in halves)
    const int arr = wm * 32 + (lane & 15);           // + mt*16
    const int acl = (lane >> 4) << 3;                // 0 or 8
    const int bnr = wn * 32 + (lane & 7) + ((lane >> 4) << 3);  // + ntp*16
    const int bcl = lane & 8;                        // 0 or 8

    for (int ch = 0; ch < NCH; ch++) {
        const int s = ch & 1;
        if (ch < NCH - 2) asm volatile("cp.async.wait_group 1;");
        else              asm volatile("cp.async.wait_group 0;");
        __syncthreads();

#pragma unroll
        for (int ks = 0; ks < 4; ks++) {
            const int wb = ks * 16;
            uint32_t Ah[2][4], Al[2][4], Bf[4][2];
#pragma unroll
            for (int mt = 0; mt < 2; mt++) {
                uint32_t ra = (uint32_t)(((arr + mt * 16) * ROWP + wb + acl) * 2);
                ldm_x4(Ah[mt], aOff[s * 2 + 0] + ra);
                ldm_x4(Al[mt], aOff[s * 2 + 1] + ra);
            }
#pragma unroll
            for (int ntp = 0; ntp < 2; ntp++) {
                uint32_t rb = (uint32_t)(((bnr + ntp * 16) * ROWP + wb + bcl) * 2);
                uint32_t rr[4];
                ldm_x4(rr, bOff[s] + rb);
                Bf[2 * ntp][0]     = rr[0];
                Bf[2 * ntp][1]     = rr[1];
                Bf[2 * ntp + 1][0] = rr[2];
                Bf[2 * ntp + 1][1] = rr[3];
            }
#pragma unroll
            for (int mt = 0; mt < 2; mt++)
#pragma unroll
                for (int nt = 0; nt < 4; nt++) {
                    mma_f16(acc[mt][nt], Ah[mt], Bf[nt]);
                    mma_f16(acc[mt][nt], Al[mt], Bf[nt]);
                }
        }
        __syncthreads();
        if (ch + 2 < NCH) load_stage(s, (ch + 2) * 64);
    }

    // ---- epilogue ----
    const float* bp = bias + (size_t)e * NDIM;
    const int gl = lane >> 2, tl = lane & 3;
#pragma unroll
    for (int mt = 0; mt < 2; mt++) {
#pragma unroll
        for (int half = 0; half < 2; half++) {
            int row = wm * 32 + mt * 16 + gl + half * 8;
            if (m0 + row < M) {
#pragma unroll
                for (int nt = 0; nt < 4; nt++) {
                    int col = n0 + wn * 32 + nt * 8 + 2 * tl;
                    float v0 = acc[mt][nt][half * 2 + 0] + bp[col];
                    float v1 = acc[mt][nt][half * 2 + 1] + bp[col + 1];
                    if (FFN1) {
                        v0 = 0.5f * v0 * (1.f + erff(v0 * 0.7071067811865476f));
                        v1 = 0.5f * v1 * (1.f + erff(v1 * 0.7071067811865476f));
                        size_t drow = (size_t)(ooff + m0 + row);
                        __half2 H, L;
                        splt(v0, H.x, L.x);
                        splt(v1, H.y, L.y);
                        *(__half2*)(Dh + drow * NDIM + col) = H;
                        *(__half2*)(Dl + drow * NDIM + col) = L;
                    } else {
                        size_t drow = (size_t)g_perm[ooff + m0 + row];
                        *(float2*)(Dout + drow * NDIM + col) = make_float2(v0, v1);
                    }
                }
            }
        }
    }
}

// ---------------- launch -----------------------------------------------------
#define GEMM_SMEM ((4 * A_ST + 2 * B_ST) * 2)   // 92160 bytes

extern "C" void kernel_launch(void* const* d_in, const int* in_sizes, int n_in,
                              void* d_out, int out_size) {
    const float* x  = (const float*)d_in[0];
    const float* Wr = (const float*)d_in[1];
    const float* br = (const float*)d_in[2];
    const float* W1 = (const float*)d_in[3];
    const float* b1 = (const float*)d_in[4];
    const float* W2 = (const float*)d_in[5];
    const float* b2 = (const float*)d_in[6];
    float* out = (float*)d_out;

    __half *xh, *xl, *w1h, *w2h, *hh, *hl;
    cudaGetSymbolAddress((void**)&xh,  g_xh);
    cudaGetSymbolAddress((void**)&xl,  g_xl);
    cudaGetSymbolAddress((void**)&w1h, g_w1h);
    cudaGetSymbolAddress((void**)&w2h, g_w2h);
    cudaGetSymbolAddress((void**)&hh,  g_hh);
    cudaGetSymbolAddress((void**)&hl,  g_hl);

    cudaFuncSetAttribute(k_gemm<DIMX, HID, true>,
                         cudaFuncAttributeMaxDynamicSharedMemorySize, GEMM_SMEM);
    cudaFuncSetAttribute(k_gemm<HID, DIMX, false>,
                         cudaFuncAttributeMaxDynamicSharedMemorySize, GEMM_SMEM);

    k_zero<<<1, 32>>>();
    k_route<<<N_TOK / 8, 256>>>(x, Wr, br);
    k_prefix<<<1, 1>>>();
    k_scatter<<<N_TOK / 256, 256>>>();

    k_split_x<<<(N_TOK * DIMX / 4) / 256, 256>>>(x, xh, xl);
    k_split_wT<<<dim3(HID / 32, DIMX / 32, NEXP), dim3(32, 8)>>>(W1, w1h, DIMX, HID);
    k_split_wT<<<dim3(DIMX / 32, HID / 32, NEXP), dim3(32, 8)>>>(W2, w2h, HID, DIMX);

    k_gemm<DIMX, HID, true ><<<dim3(HID / 64, MAXTILE, 1), 256, GEMM_SMEM>>>(
        xh, xl, w1h, b1, hh, hl, nullptr);
    k_gemm<HID, DIMX, false><<<dim3(DIMX / 64, MAXTILE, 1), 256, GEMM_SMEM>>>(
        hh, hl, w2h, b2, nullptr, nullptr, out);
}

// round 15
// speedup vs baseline: 2.7201x; 1.3290x over previous
#include <cuda_runtime.h>
#include <cuda_fp16.h>
#include <stdint.h>
#include <math.h>

#define N_TOK 32768
#define DIMX  512
#define HID   2048
#define NEXP  16
#define MAXTILE 272   // sum ceil(Me/128) <= 256 + 16

// ---------------- scratch (static device globals; no runtime allocation) ----
__device__ int g_leaf[N_TOK];
__device__ int g_cnt[NEXP];
__device__ int g_off[NEXP + 1];
__device__ int g_cur[NEXP];
__device__ int g_perm[N_TOK];
__device__ int g_tmap_e[MAXTILE];
__device__ int g_tmap_m[MAXTILE];
__device__ int g_ntile;

__device__ __half g_xh[(size_t)N_TOK * DIMX];
__device__ __half g_xl[(size_t)N_TOK * DIMX];
__device__ __half g_w1h[(size_t)NEXP * DIMX * HID];  // transposed [E][HID][DIMX]
__device__ __half g_w2h[(size_t)NEXP * DIMX * HID];  // transposed [E][DIMX][HID]
__device__ __half g_hh[(size_t)N_TOK * HID];
__device__ __half g_hl[(size_t)N_TOK * HID];

// ---------------- routing ---------------------------------------------------
__global__ void k_zero() {
    if (threadIdx.x < NEXP) g_cnt[threadIdx.x] = 0;
}

__global__ void k_route(const float* __restrict__ x,
                        const float* __restrict__ Wr,
                        const float* __restrict__ br) {
    int warp = (blockIdx.x * blockDim.x + threadIdx.x) >> 5;
    int lane = threadIdx.x & 31;
    const float4* xp = (const float4*)(x + (size_t)warp * DIMX);
    float4 xr[4];
#pragma unroll
    for (int j = 0; j < 4; j++) xr[j] = xp[lane + 32 * j];
    int leaf = 0;
#pragma unroll
    for (int d = 0; d < 4; d++) {
        int r = (1 << d) - 1 + leaf;
        const float4* wp = (const float4*)(Wr + (size_t)r * DIMX);
        float s = 0.f;
#pragma unroll
        for (int j = 0; j < 4; j++) {
            float4 w = wp[lane + 32 * j];
            s += xr[j].x * w.x; s += xr[j].y * w.y;
            s += xr[j].z * w.z; s += xr[j].w * w.w;
        }
#pragma unroll
        for (int o = 16; o; o >>= 1) s += __shfl_xor_sync(0xffffffffu, s, o);
        leaf = leaf * 2 + (((s + br[r]) > 0.f) ? 1 : 0);
    }
    if (lane == 0) {
        g_leaf[warp] = leaf;
        atomicAdd(&g_cnt[leaf], 1);
    }
}

// prefix + tile map (sum of ceil(Me/128) tiles, no empty-expert fat)
__global__ void k_prefix() {
    int acc = 0, t = 0;
    for (int e = 0; e < NEXP; e++) {
        g_off[e] = acc;
        g_cur[e] = acc;
        int c = g_cnt[e];
        for (int m = 0; m < c; m += 128) {
            g_tmap_e[t] = e;
            g_tmap_m[t] = m;
            t++;
        }
        acc += c;
    }
    g_off[NEXP] = acc;
    g_ntile = t;
    for (int i = t; i < MAXTILE; i++) { g_tmap_e[i] = -1; g_tmap_m[i] = 0; }
}

__global__ void k_scatter() {
    int n = blockIdx.x * blockDim.x + threadIdx.x;
    int pos = atomicAdd(&g_cur[g_leaf[n]], 1);
    g_perm[pos] = n;
}

// ---------------- split helpers (fp16 hi/lo) ---------------------------------
__device__ __forceinline__ void splt(float v, __half& h, __half& l) {
    h = __float2half_rn(v);
    l = __float2half_rn(v - __half2float(h));
}

__global__ void k_split_x(const float* __restrict__ x,
                          __half* __restrict__ xh,
                          __half* __restrict__ xl) {
    size_t i = (size_t)(blockIdx.x * blockDim.x + threadIdx.x) * 4;
    float4 v = *(const float4*)(x + i);
    __half2 h01, h23, l01, l23;
    splt(v.x, h01.x, l01.x); splt(v.y, h01.y, l01.y);
    splt(v.z, h23.x, l23.x); splt(v.w, h23.y, l23.y);
    *(__half2*)(xh + i)     = h01;
    *(__half2*)(xh + i + 2) = h23;
    *(__half2*)(xl + i)     = l01;
    *(__half2*)(xl + i + 2) = l23;
}

// W [E][K][N] -> transposed fp16 hi [E][N][K]
__global__ void k_split_wT(const float* __restrict__ W,
                           __half* __restrict__ Th,
                           int K, int N) {
    __shared__ float s[32][33];
    int e  = blockIdx.z;
    int k0 = blockIdx.y * 32;
    int n0 = blockIdx.x * 32;
    int tx = threadIdx.x, ty = threadIdx.y;
    const float* Wp = W + (size_t)e * K * N;
#pragma unroll
    for (int i = 0; i < 4; i++)
        s[ty + i * 8][tx] = Wp[(size_t)(k0 + ty + i * 8) * N + n0 + tx];
    __syncthreads();
    __half* ThP = Th + (size_t)e * N * K;
#pragma unroll
    for (int i = 0; i < 4; i++) {
        int rn = ty + i * 8;
        ThP[(size_t)(n0 + rn) * K + k0 + tx] = __float2half_rn(s[tx][rn]);
    }
}

// ---------------- mma / ldmatrix / cp.async ----------------------------------
__device__ __forceinline__ void mma_f16_f32(float* c, const uint32_t* a, const uint32_t* b) {
    asm volatile(
        "mma.sync.aligned.m16n8k16.row.col.f32.f16.f16.f32 "
        "{%0,%1,%2,%3}, {%4,%5,%6,%7}, {%8,%9}, {%0,%1,%2,%3};"
        : "+f"(c[0]), "+f"(c[1]), "+f"(c[2]), "+f"(c[3])
        : "r"(a[0]), "r"(a[1]), "r"(a[2]), "r"(a[3]), "r"(b[0]), "r"(b[1]));
}

__device__ __forceinline__ void mma_f16_f16(uint32_t* c, const uint32_t* a, const uint32_t* b) {
    asm volatile(
        "mma.sync.aligned.m16n8k16.row.col.f16.f16.f16.f16 "
        "{%0,%1}, {%2,%3,%4,%5}, {%6,%7}, {%0,%1};"
        : "+r"(c[0]), "+r"(c[1])
        : "r"(a[0]), "r"(a[1]), "r"(a[2]), "r"(a[3]), "r"(b[0]), "r"(b[1]));
}

__device__ __forceinline__ void ldm_x4(uint32_t* r, uint32_t addr) {
    asm volatile("ldmatrix.sync.aligned.m8n8.x4.shared.b16 {%0,%1,%2,%3}, [%4];"
                 : "=r"(r[0]), "=r"(r[1]), "=r"(r[2]), "=r"(r[3]) : "r"(addr));
}

__device__ __forceinline__ void cp16(uint32_t smem_dst, const void* gmem_src) {
    asm volatile("cp.async.cg.shared.global [%0], [%1], 16;" :: "r"(smem_dst), "l"(gmem_src));
}

// ---------------- grouped GEMM (fp16 2-product, 128x128 tile, 512 thr) -------
// D = Ah@Bh^T (f32 acc) + Al@Bh^T (f16 acc). BM=BN=128, BK=64, 3-stage ring.
// 16 warps 4(M)x4(N), warp 32x32. smem rows padded to 72 halves.
#define ROWP 72
#define TILE_H (128 * ROWP)              // halves per 128-row tile
#define STG_B  (3 * TILE_H * 2)          // bytes per stage (Ah + Al + B)
#define GEMM_SMEM (3 * STG_B)            // 165888 bytes

template<int KDIM, int NDIM, bool FFN1>
__global__ __launch_bounds__(512, 1)
void k_gemm(const __half* __restrict__ Ah_g, const __half* __restrict__ Al_g,
            const __half* __restrict__ Bh_g,
            const float* __restrict__ bias,
            __half* __restrict__ Dh, __half* __restrict__ Dl,
            float* __restrict__ Dout) {
    const int t = blockIdx.y;
    const int e = g_tmap_e[t];
    if (e < 0) return;
    const int M    = g_cnt[e];
    const int m0   = g_tmap_m[t];
    const int n0   = blockIdx.x * 128;
    const int tid  = threadIdx.x;
    const int lane = tid & 31;
    const int wm   = (tid >> 5) >> 2;    // 0..3
    const int wn   = (tid >> 5) & 3;     // 0..3
    const int ooff = g_off[e];

    extern __shared__ __half sm[];
    const uint32_t smb = (uint32_t)__cvta_generic_to_shared(sm);
    // stage s: [Ah | Al | B], each 128*ROWP halves
    auto aOffH = [&](int s) { return smb + (uint32_t)(s * STG_B); };
    auto aOffL = [&](int s) { return smb + (uint32_t)(s * STG_B + TILE_H * 2); };
    auto bOff  = [&](int s) { return smb + (uint32_t)(s * STG_B + 2 * TILE_H * 2); };

    // ---- producers: 512 threads; row = tid>>2, two 16B chunks per buffer ----
    const int prow = tid >> 2;           // 0..127
    const int pc   = (tid & 3) * 2;      // chunk pair base (16B units)
    const bool aval = (m0 + prow) < M;
    size_t arow_idx;
    if (FFN1) arow_idx = (size_t)(aval ? g_perm[ooff + m0 + prow] : 0);
    else      arow_idx = (size_t)(aval ? (ooff + m0 + prow) : 0);
    const __half* aph = Ah_g + arow_idx * KDIM;
    const __half* apl = Al_g + arow_idx * KDIM;
    const __half* bph = Bh_g + ((size_t)e * NDIM + n0 + prow) * KDIM;

    auto load_stage = [&](int s, int ke) {
        const uint32_t d = prow * ROWP * 2;
#pragma unroll
        for (int c = 0; c < 2; c++) {
            cp16(aOffH(s) + d + (pc + c) * 16, aph + ke + (pc + c) * 8);
            cp16(aOffL(s) + d + (pc + c) * 16, apl + ke + (pc + c) * 8);
            cp16(bOff(s)  + d + (pc + c) * 16, bph + ke + (pc + c) * 8);
        }
        asm volatile("cp.async.commit_group;");
    };

    float    accH[2][4][4];
    uint32_t accL[2][4][2];
#pragma unroll
    for (int mt = 0; mt < 2; mt++)
#pragma unroll
        for (int nt = 0; nt < 4; nt++) {
#pragma unroll
            for (int i = 0; i < 4; i++) accH[mt][nt][i] = 0.f;
            accL[mt][nt][0] = 0u; accL[mt][nt][1] = 0u;
        }

    constexpr int NCH = KDIM / 64;
    load_stage(0, 0);
    load_stage(1, 64);
    load_stage(2, 128);

    // ldmatrix lane geometry
    const int arr = wm * 32 + (lane & 15);                      // + mt*16
    const int acl = (lane >> 4) << 3;                           // 0 or 8
    const int bnr = wn * 32 + (lane & 7) + ((lane >> 4) << 3);  // + ntp*16
    const int bcl = lane & 8;                                   // 0 or 8

    for (int ch = 0; ch < NCH; ch++) {
        const int s = ch % 3;
        if (ch < NCH - 2)      asm volatile("cp.async.wait_group 2;");
        else if (ch == NCH - 2) asm volatile("cp.async.wait_group 1;");
        else                    asm volatile("cp.async.wait_group 0;");
        __syncthreads();

#pragma unroll
        for (int ks = 0; ks < 4; ks++) {
            const int wb = ks * 16;
            uint32_t Ah[2][4], Al[2][4], Bf[4][2];
#pragma unroll
            for (int mt = 0; mt < 2; mt++) {
                uint32_t ra = (uint32_t)(((arr + mt * 16) * ROWP + wb + acl) * 2);
                ldm_x4(Ah[mt], aOffH(s) + ra);
                ldm_x4(Al[mt], aOffL(s) + ra);
            }
#pragma unroll
            for (int ntp = 0; ntp < 2; ntp++) {
                uint32_t rb = (uint32_t)(((bnr + ntp * 16) * ROWP + wb + bcl) * 2);
                uint32_t rr[4];
                ldm_x4(rr, bOff(s) + rb);
                Bf[2 * ntp][0]     = rr[0];
                Bf[2 * ntp][1]     = rr[1];
                Bf[2 * ntp + 1][0] = rr[2];
                Bf[2 * ntp + 1][1] = rr[3];
            }
#pragma unroll
            for (int mt = 0; mt < 2; mt++)
#pragma unroll
                for (int nt = 0; nt < 4; nt++) {
                    mma_f16_f32(accH[mt][nt], Ah[mt], Bf[nt]);
                    mma_f16_f16(accL[mt][nt], Al[mt], Bf[nt]);
                }
        }
        __syncthreads();
        if (ch + 3 < NCH) load_stage(s, (ch + 3) * 64);
    }

    // ---- epilogue ----
    const float* bp = bias + (size_t)e * NDIM;
    const int gl = lane >> 2, tl = lane & 3;
#pragma unroll
    for (int mt = 0; mt < 2; mt++) {
#pragma unroll
        for (int half = 0; half < 2; half++) {
            int row = wm * 32 + mt * 16 + gl + half * 8;
            if (m0 + row < M) {
#pragma unroll
                for (int nt = 0; nt < 4; nt++) {
                    int col = n0 + wn * 32 + nt * 8 + 2 * tl;
                    float2 lo = __half22float2(*(__half2*)&accL[mt][nt][half]);
                    float v0 = accH[mt][nt][half * 2 + 0] + lo.x + bp[col];
                    float v1 = accH[mt][nt][half * 2 + 1] + lo.y + bp[col + 1];
                    if (FFN1) {
                        v0 = 0.5f * v0 * (1.f + erff(v0 * 0.7071067811865476f));
                        v1 = 0.5f * v1 * (1.f + erff(v1 * 0.7071067811865476f));
                        size_t drow = (size_t)(ooff + m0 + row);
                        __half2 H, L;
                        splt(v0, H.x, L.x);
                        splt(v1, H.y, L.y);
                        *(__half2*)(Dh + drow * NDIM + col) = H;
                        *(__half2*)(Dl + drow * NDIM + col) = L;
                    } else {
                        size_t drow = (size_t)g_perm[ooff + m0 + row];
                        *(float2*)(Dout + drow * NDIM + col) = make_float2(v0, v1);
                    }
                }
            }
        }
    }
}

// ---------------- launch -----------------------------------------------------
extern "C" void kernel_launch(void* const* d_in, const int* in_sizes, int n_in,
                              void* d_out, int out_size) {
    const float* x  = (const float*)d_in[0];
    const float* Wr = (const float*)d_in[1];
    const float* br = (const float*)d_in[2];
    const float* W1 = (const float*)d_in[3];
    const float* b1 = (const float*)d_in[4];
    const float* W2 = (const float*)d_in[5];
    const float* b2 = (const float*)d_in[6];
    float* out = (float*)d_out;

    __half *xh, *xl, *w1h, *w2h, *hh, *hl;
    cudaGetSymbolAddress((void**)&xh,  g_xh);
    cudaGetSymbolAddress((void**)&xl,  g_xl);
    cudaGetSymbolAddress((void**)&w1h, g_w1h);
    cudaGetSymbolAddress((void**)&w2h, g_w2h);
    cudaGetSymbolAddress((void**)&hh,  g_hh);
    cudaGetSymbolAddress((void**)&hl,  g_hl);

    cudaFuncSetAttribute(k_gemm<DIMX, HID, true>,
                         cudaFuncAttributeMaxDynamicSharedMemorySize, GEMM_SMEM);
    cudaFuncSetAttribute(k_gemm<HID, DIMX, false>,
                         cudaFuncAttributeMaxDynamicSharedMemorySize, GEMM_SMEM);

    k_zero<<<1, 32>>>();
    k_route<<<N_TOK / 8, 256>>>(x, Wr, br);
    k_prefix<<<1, 1>>>();
    k_scatter<<<N_TOK / 256, 256>>>();

    k_split_x<<<(N_TOK * DIMX / 4) / 256, 256>>>(x, xh, xl);
    k_split_wT<<<dim3(HID / 32, DIMX / 32, NEXP), dim3(32, 8)>>>(W1, w1h, DIMX, HID);
    k_split_wT<<<dim3(DIMX / 32, HID / 32, NEXP), dim3(32, 8)>>>(W2, w2h, HID, DIMX);

    k_gemm<DIMX, HID, true ><<<dim3(HID / 128, MAXTILE, 1), 512, GEMM_SMEM>>>(
        xh, xl, w1h, b1, hh, hl, nullptr);
    k_gemm<HID, DIMX, false><<<dim3(DIMX / 128, MAXTILE, 1), 512, GEMM_SMEM>>>(
        hh, hl, w2h, b2, nullptr, nullptr, out);
}

// round 16
// speedup vs baseline: 4.2706x; 1.5700x over previous
#include <cuda_runtime.h>
#include <cuda_fp16.h>
#include <stdint.h>
#include <math.h>

#define N_TOK 32768
#define DIMX  512
#define HID   2048
#define NEXP  16
#define MAXTILE 272   // sum ceil(Me/128) <= 256 + 16

// ---------------- scratch (static device globals; no runtime allocation) ----
__device__ int g_leaf[N_TOK];
__device__ int g_cnt[NEXP];
__device__ int g_off[NEXP + 1];
__device__ int g_cur[NEXP];
__device__ int g_perm[N_TOK];
__device__ int g_tmap_e[MAXTILE];
__device__ int g_tmap_m[MAXTILE];
__device__ int g_ntile;

__device__ __half g_xh[(size_t)N_TOK * DIMX];
__device__ __half g_w1h[(size_t)NEXP * DIMX * HID];  // transposed [E][HID][DIMX]
__device__ __half g_w2h[(size_t)NEXP * DIMX * HID];  // transposed [E][DIMX][HID]
__device__ __half g_hh[(size_t)N_TOK * HID];

// ---------------- routing (exact fp32) ---------------------------------------
__global__ void k_zero() {
    if (threadIdx.x < NEXP) g_cnt[threadIdx.x] = 0;
}

__global__ void k_route(const float* __restrict__ x,
                        const float* __restrict__ Wr,
                        const float* __restrict__ br) {
    int warp = (blockIdx.x * blockDim.x + threadIdx.x) >> 5;
    int lane = threadIdx.x & 31;
    const float4* xp = (const float4*)(x + (size_t)warp * DIMX);
    float4 xr[4];
#pragma unroll
    for (int j = 0; j < 4; j++) xr[j] = xp[lane + 32 * j];
    int leaf = 0;
#pragma unroll
    for (int d = 0; d < 4; d++) {
        int r = (1 << d) - 1 + leaf;
        const float4* wp = (const float4*)(Wr + (size_t)r * DIMX);
        float s = 0.f;
#pragma unroll
        for (int j = 0; j < 4; j++) {
            float4 w = wp[lane + 32 * j];
            s += xr[j].x * w.x; s += xr[j].y * w.y;
            s += xr[j].z * w.z; s += xr[j].w * w.w;
        }
#pragma unroll
        for (int o = 16; o; o >>= 1) s += __shfl_xor_sync(0xffffffffu, s, o);
        leaf = leaf * 2 + (((s + br[r]) > 0.f) ? 1 : 0);
    }
    if (lane == 0) {
        g_leaf[warp] = leaf;
        atomicAdd(&g_cnt[leaf], 1);
    }
}

// prefix + tile map (sum of ceil(Me/128) tiles, no empty-expert fat)
__global__ void k_prefix() {
    int acc = 0, t = 0;
    for (int e = 0; e < NEXP; e++) {
        g_off[e] = acc;
        g_cur[e] = acc;
        int c = g_cnt[e];
        for (int m = 0; m < c; m += 128) {
            g_tmap_e[t] = e;
            g_tmap_m[t] = m;
            t++;
        }
        acc += c;
    }
    g_off[NEXP] = acc;
    g_ntile = t;
    for (int i = t; i < MAXTILE; i++) { g_tmap_e[i] = -1; g_tmap_m[i] = 0; }
}

__global__ void k_scatter() {
    int n = blockIdx.x * blockDim.x + threadIdx.x;
    int pos = atomicAdd(&g_cur[g_leaf[n]], 1);
    g_perm[pos] = n;
}

// ---------------- cast kernels -----------------------------------------------
__global__ void k_cast_x(const float* __restrict__ x, __half* __restrict__ xh) {
    size_t i = (size_t)(blockIdx.x * blockDim.x + threadIdx.x) * 4;
    float4 v = *(const float4*)(x + i);
    __half2 h01 = __floats2half2_rn(v.x, v.y);
    __half2 h23 = __floats2half2_rn(v.z, v.w);
    *(__half2*)(xh + i)     = h01;
    *(__half2*)(xh + i + 2) = h23;
}

// W [E][K][N] -> transposed fp16 [E][N][K]
__global__ void k_cast_wT(const float* __restrict__ W,
                          __half* __restrict__ Th,
                          int K, int N) {
    __shared__ float s[32][33];
    int e  = blockIdx.z;
    int k0 = blockIdx.y * 32;
    int n0 = blockIdx.x * 32;
    int tx = threadIdx.x, ty = threadIdx.y;
    const float* Wp = W + (size_t)e * K * N;
#pragma unroll
    for (int i = 0; i < 4; i++)
        s[ty + i * 8][tx] = Wp[(size_t)(k0 + ty + i * 8) * N + n0 + tx];
    __syncthreads();
    __half* ThP = Th + (size_t)e * N * K;
#pragma unroll
    for (int i = 0; i < 4; i++) {
        int rn = ty + i * 8;
        ThP[(size_t)(n0 + rn) * K + k0 + tx] = __float2half_rn(s[tx][rn]);
    }
}

// ---------------- mma / ldmatrix / cp.async ----------------------------------
__device__ __forceinline__ void mma_f16_f32(float* c, const uint32_t* a, const uint32_t* b) {
    asm volatile(
        "mma.sync.aligned.m16n8k16.row.col.f32.f16.f16.f32 "
        "{%0,%1,%2,%3}, {%4,%5,%6,%7}, {%8,%9}, {%0,%1,%2,%3};"
        : "+f"(c[0]), "+f"(c[1]), "+f"(c[2]), "+f"(c[3])
        : "r"(a[0]), "r"(a[1]), "r"(a[2]), "r"(a[3]), "r"(b[0]), "r"(b[1]));
}

__device__ __forceinline__ void ldm_x4(uint32_t* r, uint32_t addr) {
    asm volatile("ldmatrix.sync.aligned.m8n8.x4.shared.b16 {%0,%1,%2,%3}, [%4];"
                 : "=r"(r[0]), "=r"(r[1]), "=r"(r[2]), "=r"(r[3]) : "r"(addr));
}

__device__ __forceinline__ void cp16(uint32_t smem_dst, const void* gmem_src) {
    asm volatile("cp.async.cg.shared.global [%0], [%1], 16;" :: "r"(smem_dst), "l"(gmem_src));
}

// ---------------- grouped GEMM (pure fp16, 128x128 tile, 512 thr) ------------
// D = A@B^T, fp32 accum. BM=BN=128, BK=64, 3-stage cp.async ring.
// 16 warps 4(M)x4(N), warp 32x32. smem rows padded to 72 halves.
#define ROWP 72
#define TILE_H (128 * ROWP)              // halves per 128-row tile
#define STG_B  (2 * TILE_H * 2)          // bytes per stage (A + B)
#define GEMM_SMEM (3 * STG_B)            // 110592 bytes

template<int KDIM, int NDIM, bool FFN1>
__global__ __launch_bounds__(512, 1)
void k_gemm(const __half* __restrict__ A_g,
            const __half* __restrict__ B_g,
            const float* __restrict__ bias,
            __half* __restrict__ Dh,
            float* __restrict__ Dout) {
    const int t = blockIdx.y;
    const int e = g_tmap_e[t];
    if (e < 0) return;
    const int M    = g_cnt[e];
    const int m0   = g_tmap_m[t];
    const int n0   = blockIdx.x * 128;
    const int tid  = threadIdx.x;
    const int lane = tid & 31;
    const int wm   = (tid >> 5) >> 2;    // 0..3
    const int wn   = (tid >> 5) & 3;     // 0..3
    const int ooff = g_off[e];

    extern __shared__ __half sm[];
    const uint32_t smb = (uint32_t)__cvta_generic_to_shared(sm);
    auto aOff = [&](int s) { return smb + (uint32_t)(s * STG_B); };
    auto bOff = [&](int s) { return smb + (uint32_t)(s * STG_B + TILE_H * 2); };

    // ---- producers: 512 threads; row = tid>>2, two 16B chunks per buffer ----
    const int prow = tid >> 2;           // 0..127
    const int pc   = (tid & 3) * 2;      // chunk pair base (16B units)
    const bool aval = (m0 + prow) < M;
    size_t arow_idx;
    if (FFN1) arow_idx = (size_t)(aval ? g_perm[ooff + m0 + prow] : 0);
    else      arow_idx = (size_t)(aval ? (ooff + m0 + prow) : 0);
    const __half* aph = A_g + arow_idx * KDIM;
    const __half* bph = B_g + ((size_t)e * NDIM + n0 + prow) * KDIM;

    auto load_stage = [&](int s, int ke) {
        const uint32_t d = prow * ROWP * 2;
#pragma unroll
        for (int c = 0; c < 2; c++) {
            cp16(aOff(s) + d + (pc + c) * 16, aph + ke + (pc + c) * 8);
            cp16(bOff(s) + d + (pc + c) * 16, bph + ke + (pc + c) * 8);
        }
        asm volatile("cp.async.commit_group;");
    };

    float acc[2][4][4];
#pragma unroll
    for (int mt = 0; mt < 2; mt++)
#pragma unroll
        for (int nt = 0; nt < 4; nt++)
#pragma unroll
            for (int i = 0; i < 4; i++) acc[mt][nt][i] = 0.f;

    constexpr int NCH = KDIM / 64;
    load_stage(0, 0);
    load_stage(1, 64);
    load_stage(2, 128);

    // ldmatrix lane geometry
    const int arr = wm * 32 + (lane & 15);                      // + mt*16
    const int acl = (lane >> 4) << 3;                           // 0 or 8
    const int bnr = wn * 32 + (lane & 7) + ((lane >> 4) << 3);  // + ntp*16
    const int bcl = lane & 8;                                   // 0 or 8

    for (int ch = 0; ch < NCH; ch++) {
        const int s = ch % 3;
        if (ch < NCH - 2)       asm volatile("cp.async.wait_group 2;");
        else if (ch == NCH - 2) asm volatile("cp.async.wait_group 1;");
        else                    asm volatile("cp.async.wait_group 0;");
        __syncthreads();

#pragma unroll
        for (int ks = 0; ks < 4; ks++) {
            const int wb = ks * 16;
            uint32_t Af[2][4], Bf[4][2];
#pragma unroll
            for (int mt = 0; mt < 2; mt++) {
                uint32_t ra = (uint32_t)(((arr + mt * 16) * ROWP + wb + acl) * 2);
                ldm_x4(Af[mt], aOff(s) + ra);
            }
#pragma unroll
            for (int ntp = 0; ntp < 2; ntp++) {
                uint32_t rb = (uint32_t)(((bnr + ntp * 16) * ROWP + wb + bcl) * 2);
                uint32_t rr[4];
                ldm_x4(rr, bOff(s) + rb);
                Bf[2 * ntp][0]     = rr[0];
                Bf[2 * ntp][1]     = rr[1];
                Bf[2 * ntp + 1][0] = rr[2];
                Bf[2 * ntp + 1][1] = rr[3];
            }
#pragma unroll
            for (int mt = 0; mt < 2; mt++)
#pragma unroll
                for (int nt = 0; nt < 4; nt++)
                    mma_f16_f32(acc[mt][nt], Af[mt], Bf[nt]);
        }
        __syncthreads();
        if (ch + 3 < NCH) load_stage(s, (ch + 3) * 64);
    }

    // ---- epilogue ----
    const float* bp = bias + (size_t)e * NDIM;
    const int gl = lane >> 2, tl = lane & 3;
#pragma unroll
    for (int mt = 0; mt < 2; mt++) {
#pragma unroll
        for (int half = 0; half < 2; half++) {
            int row = wm * 32 + mt * 16 + gl + half * 8;
            if (m0 + row < M) {
#pragma unroll
                for (int nt = 0; nt < 4; nt++) {
                    int col = n0 + wn * 32 + nt * 8 + 2 * tl;
                    float v0 = acc[mt][nt][half * 2 + 0] + bp[col];
                    float v1 = acc[mt][nt][half * 2 + 1] + bp[col + 1];
                    if (FFN1) {
                        v0 = 0.5f * v0 * (1.f + erff(v0 * 0.7071067811865476f));
                        v1 = 0.5f * v1 * (1.f + erff(v1 * 0.7071067811865476f));
                        size_t drow = (size_t)(ooff + m0 + row);
                        *(__half2*)(Dh + drow * NDIM + col) = __floats2half2_rn(v0, v1);
                    } else {
                        size_t drow = (size_t)g_perm[ooff + m0 + row];
                        *(float2*)(Dout + drow * NDIM + col) = make_float2(v0, v1);
                    }
                }
            }
        }
    }
}

// ---------------- launch -----------------------------------------------------
extern "C" void kernel_launch(void* const* d_in, const int* in_sizes, int n_in,
                              void* d_out, int out_size) {
    const float* x  = (const float*)d_in[0];
    const float* Wr = (const float*)d_in[1];
    const float* br = (const float*)d_in[2];
    const float* W1 = (const float*)d_in[3];
    const float* b1 = (const float*)d_in[4];
    const float* W2 = (const float*)d_in[5];
    const float* b2 = (const float*)d_in[6];
    float* out = (float*)d_out;

    __half *xh, *w1h, *w2h, *hh;
    cudaGetSymbolAddress((void**)&xh,  g_xh);
    cudaGetSymbolAddress((void**)&w1h, g_w1h);
    cudaGetSymbolAddress((void**)&w2h, g_w2h);
    cudaGetSymbolAddress((void**)&hh,  g_hh);

    cudaFuncSetAttribute(k_gemm<DIMX, HID, true>,
                         cudaFuncAttributeMaxDynamicSharedMemorySize, GEMM_SMEM);
    cudaFuncSetAttribute(k_gemm<HID, DIMX, false>,
                         cudaFuncAttributeMaxDynamicSharedMemorySize, GEMM_SMEM);

    k_zero<<<1, 32>>>();
    k_route<<<N_TOK / 8, 256>>>(x, Wr, br);
    k_prefix<<<1, 1>>>();
    k_scatter<<<N_TOK / 256, 256>>>();

    k_cast_x<<<(N_TOK * DIMX / 4) / 256, 256>>>(x, xh);
    k_cast_wT<<<dim3(HID / 32, DIMX / 32, NEXP), dim3(32, 8)>>>(W1, w1h, DIMX, HID);
    k_cast_wT<<<dim3(DIMX / 32, HID / 32, NEXP), dim3(32, 8)>>>(W2, w2h, HID, DIMX);

    k_gemm<DIMX, HID, true ><<<dim3(HID / 128, MAXTILE, 1), 512, GEMM_SMEM>>>(
        xh, w1h, b1, hh, nullptr);
    k_gemm<HID, DIMX, false><<<dim3(DIMX / 128, MAXTILE, 1), 512, GEMM_SMEM>>>(
        hh, w2h, b2, nullptr, out);
}